// round 7
// baseline (speedup 1.0000x reference)
#include <cuda_runtime.h>
#include <cstdint>
#include <cstddef>

// Problem constants
#define BATCH   16384
#define DIM     512
#define HID     128     // H
#define HID2    256     // 2H
#define NG      18
#define DAGG    640     // D + H

// ---------------------------------------------------------------------------
// Scratch (device globals; allocation-free rule)
// ---------------------------------------------------------------------------
__device__ float g_w[(size_t)BATCH * NG];                    // masked attention weights
__device__ float g_buf1[(size_t)NG * BATCH * HID2];          // H1c, later reused for H3c
__device__ float g_H2[(size_t)NG * BATCH * HID];             // H2c
__device__ float g_R[(size_t)BATCH * HID];                   // refinements
__device__ float g_Xr[(size_t)BATCH * DIM];                  // X rounded to tf32
__device__ float g_W1t[(size_t)NG * HID2 * DIM];             // weights: [g][N][K], tf32-rounded
__device__ float g_W2t[(size_t)NG * HID * HID2];
__device__ float g_W3t[(size_t)NG * HID * HID];
__device__ float g_Waggt[(size_t)DIM * DAGG];                // [N=512][K=640]
__device__ int   g_counts[32];                               // members per genre
__device__ int   g_idx[(size_t)NG * BATCH];                  // genre -> member rows
__device__ int   g_pos[(size_t)BATCH * NG];                  // (b,g) -> slot

// ---------------------------------------------------------------------------
// Helpers
// ---------------------------------------------------------------------------
__device__ __forceinline__ uint32_t f2tf(float f) {
    uint32_t u;
    asm("cvt.rna.tf32.f32 %0, %1;" : "=r"(u) : "f"(f));
    return u;
}
__device__ __forceinline__ float round_tf32(float f) {
    return __uint_as_float(f2tf(f));
}
__device__ __forceinline__ uint32_t smem_u32(const void* p) {
    uint32_t a;
    asm("{ .reg .u64 t; cvta.to.shared.u64 t, %1; cvt.u32.u64 %0, t; }" : "=r"(a) : "l"(p));
    return a;
}
__device__ __forceinline__ void cp_async16(uint32_t dst, const void* src) {
    asm volatile("cp.async.cg.shared.global [%0], [%1], 16;" :: "r"(dst), "l"(src) : "memory");
}
#define CP_COMMIT() asm volatile("cp.async.commit_group;" ::: "memory")
#define CP_WAIT(n)  asm volatile("cp.async.wait_group %0;" :: "n"(n) : "memory")

__device__ __forceinline__ void ldsm_x4(uint32_t addr, uint32_t* r) {
    asm volatile("ldmatrix.sync.aligned.m8n8.x4.shared.b16 {%0,%1,%2,%3}, [%4];"
        : "=r"(r[0]), "=r"(r[1]), "=r"(r[2]), "=r"(r[3]) : "r"(addr));
}

__device__ __forceinline__ void mma8(float* d, const uint32_t* a, const uint32_t* b) {
    asm volatile(
        "mma.sync.aligned.m16n8k8.row.col.f32.tf32.tf32.f32 "
        "{%0,%1,%2,%3}, {%4,%5,%6,%7}, {%8,%9}, {%0,%1,%2,%3};"
        : "+f"(d[0]), "+f"(d[1]), "+f"(d[2]), "+f"(d[3])
        : "r"(a[0]), "r"(a[1]), "r"(a[2]), "r"(a[3]), "r"(b[0]), "r"(b[1]));
}

// ---------------------------------------------------------------------------
// Prep: tf32 rounding (grid-stride float4)
// ---------------------------------------------------------------------------
__global__ __launch_bounds__(256)
void round_kernel(const float* __restrict__ in, float* __restrict__ out, int n4) {
    int i = blockIdx.x * 256 + threadIdx.x;
    int stride = gridDim.x * 256;
    for (; i < n4; i += stride) {
        float4 v = ((const float4*)in)[i];
        v.x = round_tf32(v.x); v.y = round_tf32(v.y);
        v.z = round_tf32(v.z); v.w = round_tf32(v.w);
        ((float4*)out)[i] = v;
    }
}

// ---------------------------------------------------------------------------
// Prep: transpose + tf32 round: in [g][K][N] -> out [g][N][K]
// ---------------------------------------------------------------------------
__global__ __launch_bounds__(256)
void transpose_round_kernel(const float* __restrict__ in, float* __restrict__ out,
                            int K, int N) {
    __shared__ float t[32][33];
    int g = blockIdx.z;
    in  += (size_t)g * K * N;
    out += (size_t)g * K * N;
    int k0 = blockIdx.x * 32;
    int n0 = blockIdx.y * 32;
    int tx = threadIdx.x & 31, ty = threadIdx.x >> 5;   // 32 x 8
    #pragma unroll
    for (int i = 0; i < 4; i++) {
        int r = ty + i * 8;
        t[r][tx] = round_tf32(in[(size_t)(k0 + r) * N + n0 + tx]);
    }
    __syncthreads();
    #pragma unroll
    for (int i = 0; i < 4; i++) {
        int r = ty + i * 8;
        out[(size_t)(n0 + r) * K + k0 + tx] = t[tx][r];
    }
}

// ---------------------------------------------------------------------------
// Membership compaction
// ---------------------------------------------------------------------------
__global__ __launch_bounds__(256)
void zero_kernel(int* __restrict__ counts, int* __restrict__ idxArr) {
    int t = blockIdx.x * 256 + threadIdx.x;
    if (t < 32) counts[t] = 0;
    int n4 = NG * BATCH / 4;
    for (int i = t; i < n4; i += gridDim.x * 256)
        ((int4*)idxArr)[i] = make_int4(0, 0, 0, 0);
}

__global__ __launch_bounds__(256)
void compact_kernel(const float* __restrict__ genre, int* __restrict__ counts,
                    int* __restrict__ idxArr, int* __restrict__ pos) {
    int t = blockIdx.x * 256 + threadIdx.x;   // over NG * BATCH, g-major
    int g = t >> 14;                          // BATCH = 2^14
    int b = t & (BATCH - 1);
    float gv = genre[(size_t)b * NG + g];
    unsigned mask = __ballot_sync(0xffffffffu, gv > 0.f);
    int lane = threadIdx.x & 31;
    int base = 0;
    if (lane == 0 && mask) base = atomicAdd(&counts[g], __popc(mask));
    base = __shfl_sync(0xffffffffu, base, 0);
    if (gv > 0.f) {
        int slot = base + __popc(mask & ((1u << lane) - 1u));
        idxArr[(size_t)g * BATCH + slot] = b;
        pos[(size_t)b * NG + g] = slot;
    }
}

// ---------------------------------------------------------------------------
// Attention kernel: logits = X @ Wa + ba, softmax over G, mask by membership
// ---------------------------------------------------------------------------
__global__ __launch_bounds__(256)
void attn_kernel(const float* __restrict__ X, const float* __restrict__ genre,
                 const float* __restrict__ Wa, const float* __restrict__ ba,
                 float* __restrict__ w) {
    __shared__ float Was[DIM * 19];
    __shared__ float bas[32];
    int tid = threadIdx.x;
    for (int i = tid; i < DIM * NG; i += 256) {
        int d = i / NG, g = i % NG;
        Was[d * 19 + g] = Wa[i];
    }
    if (tid < NG) bas[tid] = ba[tid];
    __syncthreads();

    int warp = tid >> 5, lane = tid & 31;
    for (int it = 0; it < 8; ++it) {
        int b = blockIdx.x * 64 + it * 8 + warp;
        float acc[NG];
        #pragma unroll
        for (int g = 0; g < NG; g++) acc[g] = 0.f;
        #pragma unroll
        for (int i = 0; i < 16; i++) {
            int d = 32 * i + lane;
            float xv = X[(size_t)b * DIM + d];
            const float* wrow = &Was[d * 19];
            #pragma unroll
            for (int g = 0; g < NG; g++) acc[g] += xv * wrow[g];
        }
        #pragma unroll
        for (int off = 16; off > 0; off >>= 1) {
            #pragma unroll
            for (int g = 0; g < NG; g++)
                acc[g] += __shfl_xor_sync(0xffffffffu, acc[g], off);
        }
        #pragma unroll
        for (int g = 0; g < NG; g++) acc[g] += bas[g];
        float mx = acc[0];
        #pragma unroll
        for (int g = 1; g < NG; g++) mx = fmaxf(mx, acc[g]);
        float s = 0.f, e_own = 0.f;
        #pragma unroll
        for (int g = 0; g < NG; g++) {
            float e = expf(acc[g] - mx);
            s += e;
            if (g == lane) e_own = e;
        }
        if (lane < NG) {
            float attn = e_own / s;
            float gv = genre[(size_t)b * NG + lane];
            w[(size_t)b * NG + lane] = (gv > 0.f) ? attn * gv : 0.f;
        }
    }
}

// ---------------------------------------------------------------------------
// tf32 GEMM (mma.sync + ldmatrix fragments, cp.async double-buffered).
// W is [N][K] (n-major). Fragments loaded via ldmatrix.m8n8.x4.b16:
//   A (row-major smem): one x4 = full m16k8 fragment {a0,a1,a2,a3}
//   B (n-major smem):   one x4 = {b0,b1} for two adjacent n8 tiles
// MODE: 1 = gather-A rows via idx + early-exit; 2 = dense + early-exit;
//       3 = concat [X|R] along K.
// Block tile 128x128, K-chunk 32, 8 warps (4x2), warp tile 32x64.
// ---------------------------------------------------------------------------
#define BM 128
#define BN 128
#define BK 32
#define LDAS 36
#define LDBS 36
#define ASZ (BM * LDAS)
#define BSZ (BN * LDBS)
#define GEMM_SMEM_BYTES ((2 * ASZ + 2 * BSZ) * 4)

template<int ACT, int ROUND, int MODE>
__global__ __launch_bounds__(256, 2)
void gemm_tf32_kernel(const float* __restrict__ A, const float* __restrict__ Rp,
                      const float* __restrict__ W, const float* __restrict__ bias,
                      float* __restrict__ C,
                      int M, int N, int K, int lda,
                      long long sA, long long sW, long long sB, long long sC,
                      const int* __restrict__ idxArr, const int* __restrict__ counts) {
    int g = blockIdx.z;
    int m0 = blockIdx.x * BM;
    if (MODE == 1 || MODE == 2) {
        if (m0 >= counts[g]) return;
    }
    A    += (size_t)g * sA;
    W    += (size_t)g * sW;
    bias += (size_t)g * sB;
    C    += (size_t)g * sC;
    const int* gidx = idxArr + (size_t)g * BATCH;

    extern __shared__ float sm[];
    float* As = sm;                 // [2][ASZ]  row-major [m][k], pad 36
    float* Bs = sm + 2 * ASZ;       // [2][BSZ]  n-major  [n][k], pad 36
    uint32_t as_u = smem_u32(As);
    uint32_t bs_u = smem_u32(Bs);

    int tid  = threadIdx.x;
    int n0   = blockIdx.y * BN;
    int lane = tid & 31, warp = tid >> 5;
    int wm_base = (warp >> 1) * 32;
    int wn_base = (warp & 1) * 64;

    float acc[2][8][4];
    #pragma unroll
    for (int i = 0; i < 2; i++)
        #pragma unroll
        for (int j = 0; j < 8; j++)
            #pragma unroll
            for (int r = 0; r < 4; r++) acc[i][j][r] = 0.f;

    int ar = tid >> 3, ac = (tid & 7) * 4;     // A loader: 32 rows x 8 float4
    int bn = tid >> 1, bk = (tid & 1) * 16;    // B loader: 128 n-rows, 2 threads/row

    // Pre-resolve gathered row pointers for this thread's 4 A rows
    const float* arow_ptr[4];
    #pragma unroll
    for (int rr = 0; rr < 4; rr++) {
        int r = ar + rr * 32;
        int grow = m0 + r;
        if (MODE == 1) {
            int srcrow = gidx[grow];
            arow_ptr[rr] = A + (size_t)srcrow * lda;
        } else {
            arow_ptr[rr] = A + (size_t)grow * lda;
        }
    }

    // ldmatrix lane address offsets (bytes, without kb and buffer base)
    int lane8 = lane & 7;
    int a_hi8 = ((lane >> 3) & 1) * 8;   // +8 rows for matrices 1,3
    int a_kh  = (lane >> 4) * 4;         // k-half for matrices 2,3
    uint32_t a_off[2];
    #pragma unroll
    for (int wm = 0; wm < 2; wm++)
        a_off[wm] = (uint32_t)(((wm_base + wm * 16 + a_hi8 + lane8) * LDAS + a_kh) * 4);
    int b_hi8 = (lane >> 4) * 8;         // +8 n-rows for matrices 2,3
    int b_kh  = ((lane >> 3) & 1) * 4;   // k-half for matrices 1,3
    uint32_t b_off[4];
    #pragma unroll
    for (int wnp = 0; wnp < 4; wnp++)
        b_off[wnp] = (uint32_t)(((wn_base + wnp * 16 + b_hi8 + lane8) * LDBS + b_kh) * 4);

    int nchunks = K / BK;

    auto stage = [&](int bsel, int k0) {
        uint32_t abase = as_u + (uint32_t)bsel * ASZ * 4;
        #pragma unroll
        for (int rr = 0; rr < 4; rr++) {
            int r = ar + rr * 32;
            int gcol = k0 + ac;
            const float* src;
            if (MODE == 3) {
                int grow = m0 + r;
                src = (gcol < DIM) ? (A + (size_t)grow * DIM + gcol)
                                   : (Rp + (size_t)grow * HID + (gcol - DIM));
            } else {
                src = arow_ptr[rr] + gcol;
            }
            cp_async16(abase + (uint32_t)(r * LDAS + ac) * 4, src);
        }
        uint32_t bbase = bs_u + (uint32_t)bsel * BSZ * 4;
        const float* wsrc = W + (size_t)(n0 + bn) * K + k0 + bk;
        #pragma unroll
        for (int j = 0; j < 4; j++) {
            cp_async16(bbase + (uint32_t)(bn * LDBS + bk + j * 4) * 4, wsrc + j * 4);
        }
    };

    stage(0, 0);
    CP_COMMIT();

    for (int c = 0; c < nchunks; c++) {
        int cur = c & 1;
        if (c + 1 < nchunks) {
            stage(cur ^ 1, (c + 1) * BK);
            CP_COMMIT();
            CP_WAIT(1);
        } else {
            CP_WAIT(0);
        }
        __syncthreads();

        uint32_t ab = as_u + (uint32_t)cur * ASZ * 4;
        uint32_t bb = bs_u + (uint32_t)cur * BSZ * 4;

        #pragma unroll
        for (int kk = 0; kk < 4; kk++) {
            uint32_t kb4 = (uint32_t)(kk * 8 * 4);
            uint32_t af[2][4], bf[4][4];
            ldsm_x4(ab + a_off[0] + kb4, af[0]);
            ldsm_x4(ab + a_off[1] + kb4, af[1]);
            #pragma unroll
            for (int wnp = 0; wnp < 4; wnp++)
                ldsm_x4(bb + b_off[wnp] + kb4, bf[wnp]);
            #pragma unroll
            for (int wm = 0; wm < 2; wm++)
                #pragma unroll
                for (int wnp = 0; wnp < 4; wnp++) {
                    mma8(acc[wm][2 * wnp],     af[wm], &bf[wnp][0]);
                    mma8(acc[wm][2 * wnp + 1], af[wm], &bf[wnp][2]);
                }
        }
        __syncthreads();
    }

    // ---- epilogue: + bias, optional relu, optional tf32 round, write ----
    #pragma unroll
    for (int wm = 0; wm < 2; wm++) {
        int r0 = m0 + wm_base + wm * 16 + (lane >> 2);
        #pragma unroll
        for (int wn = 0; wn < 8; wn++) {
            int c0 = n0 + wn_base + wn * 8 + 2 * (lane & 3);
            float b0 = bias[c0], b1v = bias[c0 + 1];
            float v0 = acc[wm][wn][0] + b0;
            float v1 = acc[wm][wn][1] + b1v;
            float v2 = acc[wm][wn][2] + b0;
            float v3 = acc[wm][wn][3] + b1v;
            if (ACT) {
                v0 = fmaxf(v0, 0.f); v1 = fmaxf(v1, 0.f);
                v2 = fmaxf(v2, 0.f); v3 = fmaxf(v3, 0.f);
            }
            if (ROUND) {
                v0 = round_tf32(v0); v1 = round_tf32(v1);
                v2 = round_tf32(v2); v3 = round_tf32(v3);
            }
            float2 p0 = make_float2(v0, v1);
            float2 p1 = make_float2(v2, v3);
            *(float2*)(C + (size_t)r0 * N + c0)       = p0;
            *(float2*)(C + (size_t)(r0 + 8) * N + c0) = p1;
        }
    }
}

// ---------------------------------------------------------------------------
// Weighted reduce (compacted): R[b,:] = sum_g w[b,g] * H3c[g, pos[b,g], :]
// ---------------------------------------------------------------------------
__global__ __launch_bounds__(256)
void reduce_kernel(const float* __restrict__ H3, const float* __restrict__ w,
                   const int* __restrict__ pos, float* __restrict__ R) {
    int idx = blockIdx.x * blockDim.x + threadIdx.x;   // over BATCH * 32 float4s
    int b = idx >> 5;
    int off = idx & 31;
    float4 r = make_float4(0.f, 0.f, 0.f, 0.f);
    const float4* H = (const float4*)H3;
    #pragma unroll
    for (int g = 0; g < NG; g++) {
        float wv = w[(size_t)b * NG + g];
        if (wv != 0.f) {
            int slot = pos[(size_t)b * NG + g];
            float4 h = H[((size_t)g * BATCH + slot) * 32 + off];
            r.x += wv * h.x; r.y += wv * h.y;
            r.z += wv * h.z; r.w += wv * h.w;
        }
    }
    r.x = round_tf32(r.x); r.y = round_tf32(r.y);
    r.z = round_tf32(r.z); r.w = round_tf32(r.w);
    ((float4*)R)[idx] = r;
}

// ---------------------------------------------------------------------------
// Launch
// ---------------------------------------------------------------------------
extern "C" void kernel_launch(void* const* d_in, const int* in_sizes, int n_in,
                              void* d_out, int out_size) {
    (void)in_sizes; (void)n_in; (void)out_size;
    const float* X     = (const float*)d_in[0];
    const float* genre = (const float*)d_in[1];
    const float* W1    = (const float*)d_in[2];
    const float* b1    = (const float*)d_in[3];
    const float* W2    = (const float*)d_in[4];
    const float* b2    = (const float*)d_in[5];
    const float* W3    = (const float*)d_in[6];
    const float* b3    = (const float*)d_in[7];
    const float* Wa    = (const float*)d_in[8];
    const float* ba    = (const float*)d_in[9];
    const float* Wagg  = (const float*)d_in[10];
    const float* bagg  = (const float*)d_in[11];
    float* out = (float*)d_out;

    float *w, *buf1, *H2, *R, *Xr, *W1t, *W2t, *W3t, *Waggt;
    int *counts, *idxArr, *pos;
    cudaGetSymbolAddress((void**)&w,      g_w);
    cudaGetSymbolAddress((void**)&buf1,   g_buf1);
    cudaGetSymbolAddress((void**)&H2,     g_H2);
    cudaGetSymbolAddress((void**)&R,      g_R);
    cudaGetSymbolAddress((void**)&Xr,     g_Xr);
    cudaGetSymbolAddress((void**)&W1t,    g_W1t);
    cudaGetSymbolAddress((void**)&W2t,    g_W2t);
    cudaGetSymbolAddress((void**)&W3t,    g_W3t);
    cudaGetSymbolAddress((void**)&Waggt,  g_Waggt);
    cudaGetSymbolAddress((void**)&counts, g_counts);
    cudaGetSymbolAddress((void**)&idxArr, g_idx);
    cudaGetSymbolAddress((void**)&pos,    g_pos);

    // Unconditional (idempotent, host-side, not captured) — no static guards.
    cudaFuncSetAttribute(gemm_tf32_kernel<1, 1, 1>,
                         cudaFuncAttributeMaxDynamicSharedMemorySize, GEMM_SMEM_BYTES);
    cudaFuncSetAttribute(gemm_tf32_kernel<1, 1, 2>,
                         cudaFuncAttributeMaxDynamicSharedMemorySize, GEMM_SMEM_BYTES);
    cudaFuncSetAttribute(gemm_tf32_kernel<0, 0, 2>,
                         cudaFuncAttributeMaxDynamicSharedMemorySize, GEMM_SMEM_BYTES);
    cudaFuncSetAttribute(gemm_tf32_kernel<1, 0, 3>,
                         cudaFuncAttributeMaxDynamicSharedMemorySize, GEMM_SMEM_BYTES);

    // 0) prep: round X; transpose+round all weights to [N][K]; compaction
    round_kernel<<<512, 256>>>(X, Xr, BATCH * DIM / 4);
    transpose_round_kernel<<<dim3(DIM / 32, HID2 / 32, NG), 256>>>(W1, W1t, DIM, HID2);
    transpose_round_kernel<<<dim3(HID2 / 32, HID / 32, NG), 256>>>(W2, W2t, HID2, HID);
    transpose_round_kernel<<<dim3(HID / 32, HID / 32, NG), 256>>>(W3, W3t, HID, HID);
    transpose_round_kernel<<<dim3(DAGG / 32, DIM / 32, 1), 256>>>(Wagg, Waggt, DAGG, DIM);
    zero_kernel<<<288, 256>>>(counts, idxArr);
    compact_kernel<<<NG * BATCH / 256, 256>>>(genre, counts, idxArr, pos);

    // 1) attention weights (masked)
    attn_kernel<<<BATCH / 64, 256>>>(X, genre, Wa, ba, w);

    // 2) H1c = relu(gather(Xr) @ W1[g] + b1[g])  [compacted rows]
    gemm_tf32_kernel<1, 1, 1><<<dim3(BATCH / BM, HID2 / BN, NG), 256, GEMM_SMEM_BYTES>>>(
        Xr, nullptr, W1t, b1, buf1,
        BATCH, HID2, DIM, DIM,
        0LL, (long long)DIM * HID2, HID2, (long long)BATCH * HID2,
        idxArr, counts);

    // 3) H2c = relu(H1c @ W2[g] + b2[g])
    gemm_tf32_kernel<1, 1, 2><<<dim3(BATCH / BM, 1, NG), 256, GEMM_SMEM_BYTES>>>(
        buf1, nullptr, W2t, b2, H2,
        BATCH, HID, HID2, HID2,
        (long long)BATCH * HID2, (long long)HID2 * HID, HID, (long long)BATCH * HID,
        idxArr, counts);

    // 4) H3c = H2c @ W3[g] + b3[g]   (reuse buf1)
    gemm_tf32_kernel<0, 0, 2><<<dim3(BATCH / BM, 1, NG), 256, GEMM_SMEM_BYTES>>>(
        H2, nullptr, W3t, b3, buf1,
        BATCH, HID, HID, HID,
        (long long)BATCH * HID, (long long)HID * HID, HID, (long long)BATCH * HID,
        idxArr, counts);

    // 5) R = sum_g w .* H3c[pos]
    reduce_kernel<<<(BATCH * 32) / 256, 256>>>(buf1, w, pos, R);

    // 6) out = relu([Xr, R] @ Wagg + bagg)
    gemm_tf32_kernel<1, 0, 3><<<dim3(BATCH / BM, DIM / BN, 1), 256, GEMM_SMEM_BYTES>>>(
        Xr, R, Waggt, bagg, out,
        BATCH, DIM, DAGG, DAGG,
        0LL, 0LL, 0LL, 0LL,
        idxArr, counts);
}

// round 9
// speedup vs baseline: 1.6987x; 1.6987x over previous
#include <cuda_runtime.h>
#include <cuda_fp16.h>
#include <cstdint>
#include <cstddef>

// Problem constants
#define BATCH   16384
#define DIM     512
#define HID     128     // H
#define HID2    256     // 2H
#define NG      18
#define DAGG    640     // D + H

// ---------------------------------------------------------------------------
// Scratch (device globals; allocation-free rule)
// ---------------------------------------------------------------------------
__device__ float  g_w[(size_t)BATCH * NG];                   // masked attention weights
__device__ __half g_Xh[(size_t)BATCH * DIM];                 // X cast to fp16
__device__ __half g_W1h[(size_t)NG * HID2 * DIM];            // weights n-major [g][N][K] fp16
__device__ __half g_W2h[(size_t)NG * HID * HID2];
__device__ __half g_W3h[(size_t)NG * HID * HID];
__device__ __half g_Waggh[(size_t)DIM * DAGG];               // [N=512][K=640]
__device__ __half g_H1h[(size_t)NG * BATCH * HID2];          // H1 compacted, fp16
__device__ __half g_H2h[(size_t)NG * BATCH * HID];           // H2 compacted, fp16
__device__ float  g_H3f[(size_t)NG * BATCH * HID];           // H3 compacted, fp32
__device__ __half g_Rh[(size_t)BATCH * HID];                 // refinements fp16
__device__ int    g_counts[32];                              // members per genre
__device__ int    g_idx[(size_t)NG * BATCH];                 // genre -> member rows
__device__ int    g_pos[(size_t)BATCH * NG];                 // (b,g) -> slot

// ---------------------------------------------------------------------------
// Helpers
// ---------------------------------------------------------------------------
__device__ __forceinline__ uint32_t smem_u32(const void* p) {
    uint32_t a;
    asm("{ .reg .u64 t; cvta.to.shared.u64 t, %1; cvt.u32.u64 %0, t; }" : "=r"(a) : "l"(p));
    return a;
}
__device__ __forceinline__ void cp_async16(uint32_t dst, const void* src) {
    asm volatile("cp.async.cg.shared.global [%0], [%1], 16;" :: "r"(dst), "l"(src) : "memory");
}
#define CP_COMMIT() asm volatile("cp.async.commit_group;" ::: "memory")
#define CP_WAIT(n)  asm volatile("cp.async.wait_group %0;" :: "n"(n) : "memory")

// fp16 MMA m16n8k16, fp32 accumulate
__device__ __forceinline__ void mma16(float* d, const uint32_t* a, const uint32_t* b) {
    asm volatile(
        "mma.sync.aligned.m16n8k16.row.col.f32.f16.f16.f32 "
        "{%0,%1,%2,%3}, {%4,%5,%6,%7}, {%8,%9}, {%0,%1,%2,%3};"
        : "+f"(d[0]), "+f"(d[1]), "+f"(d[2]), "+f"(d[3])
        : "r"(a[0]), "r"(a[1]), "r"(a[2]), "r"(a[3]), "r"(b[0]), "r"(b[1]));
}

// ---------------------------------------------------------------------------
// Prep: cast X to fp16 (grid-stride over float4 -> 4 halfs)
// ---------------------------------------------------------------------------
__global__ __launch_bounds__(256)
void cast_x_kernel(const float* __restrict__ in, __half* __restrict__ out, int n4) {
    int i = blockIdx.x * 256 + threadIdx.x;
    int stride = gridDim.x * 256;
    for (; i < n4; i += stride) {
        float4 v = ((const float4*)in)[i];
        __half2 h0 = __floats2half2_rn(v.x, v.y);
        __half2 h1 = __floats2half2_rn(v.z, v.w);
        uint2 p;
        p.x = *(uint32_t*)&h0;
        p.y = *(uint32_t*)&h1;
        ((uint2*)out)[i] = p;
    }
}

// ---------------------------------------------------------------------------
// Prep: transpose + cast: in fp32 [g][K][N] -> out fp16 [g][N][K]
// ---------------------------------------------------------------------------
__global__ __launch_bounds__(256)
void transpose_cast_kernel(const float* __restrict__ in, __half* __restrict__ out,
                           int K, int N) {
    __shared__ float t[32][33];
    int g = blockIdx.z;
    in  += (size_t)g * K * N;
    out += (size_t)g * K * N;
    int k0 = blockIdx.x * 32;
    int n0 = blockIdx.y * 32;
    int tx = threadIdx.x & 31, ty = threadIdx.x >> 5;   // 32 x 8
    #pragma unroll
    for (int i = 0; i < 4; i++) {
        int r = ty + i * 8;
        t[r][tx] = in[(size_t)(k0 + r) * N + n0 + tx];
    }
    __syncthreads();
    #pragma unroll
    for (int i = 0; i < 4; i++) {
        int r = ty + i * 8;
        out[(size_t)(n0 + r) * K + k0 + tx] = __float2half_rn(t[tx][r]);
    }
}

// ---------------------------------------------------------------------------
// Membership compaction
// ---------------------------------------------------------------------------
__global__ __launch_bounds__(256)
void zero_kernel(int* __restrict__ counts, int* __restrict__ idxArr) {
    int t = blockIdx.x * 256 + threadIdx.x;
    if (t < 32) counts[t] = 0;
    int n4 = NG * BATCH / 4;
    for (int i = t; i < n4; i += gridDim.x * 256)
        ((int4*)idxArr)[i] = make_int4(0, 0, 0, 0);
}

__global__ __launch_bounds__(256)
void compact_kernel(const float* __restrict__ genre, int* __restrict__ counts,
                    int* __restrict__ idxArr, int* __restrict__ pos) {
    int t = blockIdx.x * 256 + threadIdx.x;   // over NG * BATCH, g-major
    int g = t >> 14;                          // BATCH = 2^14
    int b = t & (BATCH - 1);
    float gv = genre[(size_t)b * NG + g];
    unsigned mask = __ballot_sync(0xffffffffu, gv > 0.f);
    int lane = threadIdx.x & 31;
    int base = 0;
    if (lane == 0 && mask) base = atomicAdd(&counts[g], __popc(mask));
    base = __shfl_sync(0xffffffffu, base, 0);
    if (gv > 0.f) {
        int slot = base + __popc(mask & ((1u << lane) - 1u));
        idxArr[(size_t)g * BATCH + slot] = b;
        pos[(size_t)b * NG + g] = slot;
    }
}

// ---------------------------------------------------------------------------
// Attention kernel (fp32): logits = X @ Wa + ba, softmax over G, mask
// ---------------------------------------------------------------------------
__global__ __launch_bounds__(256)
void attn_kernel(const float* __restrict__ X, const float* __restrict__ genre,
                 const float* __restrict__ Wa, const float* __restrict__ ba,
                 float* __restrict__ w) {
    __shared__ float Was[DIM * 19];
    __shared__ float bas[32];
    int tid = threadIdx.x;
    for (int i = tid; i < DIM * NG; i += 256) {
        int d = i / NG, g = i % NG;
        Was[d * 19 + g] = Wa[i];
    }
    if (tid < NG) bas[tid] = ba[tid];
    __syncthreads();

    int warp = tid >> 5, lane = tid & 31;
    for (int it = 0; it < 8; ++it) {
        int b = blockIdx.x * 64 + it * 8 + warp;
        float acc[NG];
        #pragma unroll
        for (int g = 0; g < NG; g++) acc[g] = 0.f;
        #pragma unroll
        for (int i = 0; i < 16; i++) {
            int d = 32 * i + lane;
            float xv = X[(size_t)b * DIM + d];
            const float* wrow = &Was[d * 19];
            #pragma unroll
            for (int g = 0; g < NG; g++) acc[g] += xv * wrow[g];
        }
        #pragma unroll
        for (int off = 16; off > 0; off >>= 1) {
            #pragma unroll
            for (int g = 0; g < NG; g++)
                acc[g] += __shfl_xor_sync(0xffffffffu, acc[g], off);
        }
        #pragma unroll
        for (int g = 0; g < NG; g++) acc[g] += bas[g];
        float mx = acc[0];
        #pragma unroll
        for (int g = 1; g < NG; g++) mx = fmaxf(mx, acc[g]);
        float s = 0.f, e_own = 0.f;
        #pragma unroll
        for (int g = 0; g < NG; g++) {
            float e = expf(acc[g] - mx);
            s += e;
            if (g == lane) e_own = e;
        }
        if (lane < NG) {
            float attn = e_own / s;
            float gv = genre[(size_t)b * NG + lane];
            w[(size_t)b * NG + lane] = (gv > 0.f) ? attn * gv : 0.f;
        }
    }
}

// ---------------------------------------------------------------------------
// fp16 GEMM (mma.sync m16n8k16, cp.async double-buffered).
// A: [M][K] fp16 row-major (k-major). W: [N][K] fp16 n-major. fp32 accum.
// MODE: 1 = gather-A rows via idx + early-exit; 2 = dense + early-exit;
//       3 = concat [Xh | Rh] along K (chunks 0-7 X, 8-9 R).
// OUTH: 1 = write fp16, 0 = write fp32.
// Block tile 128x128, K-chunk 64, 8 warps (4x2), warp tile 32x64.
// ---------------------------------------------------------------------------
#define BM  128
#define BN  128
#define BKH 64
#define LDH 72                      // half stride per row (64 + 8 pad)
#define TSZ (128 * LDH)             // halves per tile
#define GEMM_SMEM_BYTES (4 * TSZ * 2)   // 2 stages x (A + B) x 2B

template<int ACT, int OUTH, int MODE>
__global__ __launch_bounds__(256, 2)
void gemm_fp16_kernel(const __half* __restrict__ A, const __half* __restrict__ Rp,
                      const __half* __restrict__ W, const float* __restrict__ bias,
                      void* __restrict__ Cv,
                      int N, int K, int lda,
                      long long sA, long long sW, long long sB, long long sC,
                      const int* __restrict__ idxArr, const int* __restrict__ counts) {
    int g = blockIdx.z;
    int m0 = blockIdx.x * BM;
    if (MODE == 1 || MODE == 2) {
        if (m0 >= counts[g]) return;
    }
    A    += (size_t)g * sA;
    W    += (size_t)g * sW;
    bias += (size_t)g * sB;
    const int* gidx = idxArr + (size_t)g * BATCH;

    extern __shared__ __half smh[];
    __half* As = smh;               // [2][TSZ]  [m][k] pad LDH
    __half* Bs = smh + 2 * TSZ;     // [2][TSZ]  [n][k] pad LDH
    uint32_t as_u = smem_u32(As);
    uint32_t bs_u = smem_u32(Bs);

    int tid  = threadIdx.x;
    int n0   = blockIdx.y * BN;
    int lane = tid & 31, warp = tid >> 5;
    int wm_base = (warp >> 1) * 32;
    int wn_base = (warp & 1) * 64;

    float acc[2][8][4];
    #pragma unroll
    for (int i = 0; i < 2; i++)
        #pragma unroll
        for (int j = 0; j < 8; j++)
            #pragma unroll
            for (int r = 0; r < 4; r++) acc[i][j][r] = 0.f;

    // Loaders: 32 rows per pass x 8 threads/row x 8 halfs (16B)
    int lr = tid >> 3, lc = (tid & 7) * 8;

    // Pre-resolve gathered row pointers for this thread's 4 A rows (MODE 1/2)
    const __half* arow_ptr[4];
    #pragma unroll
    for (int rr = 0; rr < 4; rr++) {
        int grow = m0 + lr + rr * 32;
        if (MODE == 1) {
            arow_ptr[rr] = A + (size_t)gidx[grow] * lda;
        } else {
            arow_ptr[rr] = A + (size_t)grow * lda;
        }
    }

    int nchunks = K / BKH;

    auto stage = [&](int bsel, int k0) {
        uint32_t abase = as_u + (uint32_t)(bsel * TSZ) * 2;
        #pragma unroll
        for (int rr = 0; rr < 4; rr++) {
            int r = lr + rr * 32;
            int gcol = k0 + lc;
            const __half* src;
            if (MODE == 3) {
                int grow = m0 + r;
                src = (gcol < DIM) ? (A + (size_t)grow * DIM + gcol)
                                   : (Rp + (size_t)grow * HID + (gcol - DIM));
            } else {
                src = arow_ptr[rr] + gcol;
            }
            cp_async16(abase + (uint32_t)(r * LDH + lc) * 2, src);
        }
        uint32_t bbase = bs_u + (uint32_t)(bsel * TSZ) * 2;
        #pragma unroll
        for (int rr = 0; rr < 4; rr++) {
            int n = lr + rr * 32;
            cp_async16(bbase + (uint32_t)(n * LDH + lc) * 2,
                       W + (size_t)(n0 + n) * K + k0 + lc);
        }
    };

    stage(0, 0);
    CP_COMMIT();

    for (int c = 0; c < nchunks; c++) {
        int cur = c & 1;
        if (c + 1 < nchunks) {
            stage(cur ^ 1, (c + 1) * BKH);
            CP_COMMIT();
            CP_WAIT(1);
        } else {
            CP_WAIT(0);
        }
        __syncthreads();

        const __half* Ab = As + cur * TSZ;
        const __half* Bb = Bs + cur * TSZ;

        #pragma unroll
        for (int kk = 0; kk < 4; kk++) {
            int kc = kk * 16 + 2 * (lane & 3);
            uint32_t af[2][4], bf[8][2];
            #pragma unroll
            for (int wm = 0; wm < 2; wm++) {
                int r = wm_base + wm * 16 + (lane >> 2);
                af[wm][0] = *(const uint32_t*)(Ab + r * LDH + kc);
                af[wm][1] = *(const uint32_t*)(Ab + (r + 8) * LDH + kc);
                af[wm][2] = *(const uint32_t*)(Ab + r * LDH + kc + 8);
                af[wm][3] = *(const uint32_t*)(Ab + (r + 8) * LDH + kc + 8);
            }
            #pragma unroll
            for (int wn = 0; wn < 8; wn++) {
                int n = wn_base + wn * 8 + (lane >> 2);
                bf[wn][0] = *(const uint32_t*)(Bb + n * LDH + kc);
                bf[wn][1] = *(const uint32_t*)(Bb + n * LDH + kc + 8);
            }
            #pragma unroll
            for (int wm = 0; wm < 2; wm++)
                #pragma unroll
                for (int wn = 0; wn < 8; wn++)
                    mma16(acc[wm][wn], af[wm], bf[wn]);
        }
        __syncthreads();
    }

    // ---- epilogue: + bias, optional relu, write fp16 or fp32 ----
    #pragma unroll
    for (int wm = 0; wm < 2; wm++) {
        int r0 = m0 + wm_base + wm * 16 + (lane >> 2);
        #pragma unroll
        for (int wn = 0; wn < 8; wn++) {
            int c0 = n0 + wn_base + wn * 8 + 2 * (lane & 3);
            float b0 = bias[c0], b1v = bias[c0 + 1];
            float v0 = acc[wm][wn][0] + b0;
            float v1 = acc[wm][wn][1] + b1v;
            float v2 = acc[wm][wn][2] + b0;
            float v3 = acc[wm][wn][3] + b1v;
            if (ACT) {
                v0 = fmaxf(v0, 0.f); v1 = fmaxf(v1, 0.f);
                v2 = fmaxf(v2, 0.f); v3 = fmaxf(v3, 0.f);
            }
            if (OUTH) {
                __half* C = (__half*)Cv + (size_t)g * sC;
                __half2 p0 = __floats2half2_rn(v0, v1);
                __half2 p1 = __floats2half2_rn(v2, v3);
                *(__half2*)(C + (size_t)r0 * N + c0)       = p0;
                *(__half2*)(C + (size_t)(r0 + 8) * N + c0) = p1;
            } else {
                float* C = (float*)Cv + (size_t)g * sC;
                *(float2*)(C + (size_t)r0 * N + c0)       = make_float2(v0, v1);
                *(float2*)(C + (size_t)(r0 + 8) * N + c0) = make_float2(v2, v3);
            }
        }
    }
}

// ---------------------------------------------------------------------------
// Weighted reduce (compacted): Rh[b,:] = fp16( sum_g w[b,g] * H3f[g, pos[b,g], :] )
// ---------------------------------------------------------------------------
__global__ __launch_bounds__(256)
void reduce_kernel(const float* __restrict__ H3, const float* __restrict__ w,
                   const int* __restrict__ pos, __half* __restrict__ Rh) {
    int idx = blockIdx.x * blockDim.x + threadIdx.x;   // over BATCH * 32 float4s
    int b = idx >> 5;
    int off = idx & 31;
    float4 r = make_float4(0.f, 0.f, 0.f, 0.f);
    const float4* H = (const float4*)H3;
    #pragma unroll
    for (int g = 0; g < NG; g++) {
        float wv = w[(size_t)b * NG + g];
        if (wv != 0.f) {
            int slot = pos[(size_t)b * NG + g];
            float4 h = H[((size_t)g * BATCH + slot) * 32 + off];
            r.x += wv * h.x; r.y += wv * h.y;
            r.z += wv * h.z; r.w += wv * h.w;
        }
    }
    __half2 p0 = __floats2half2_rn(r.x, r.y);
    __half2 p1 = __floats2half2_rn(r.z, r.w);
    uint2 p;
    p.x = *(uint32_t*)&p0;
    p.y = *(uint32_t*)&p1;
    ((uint2*)Rh)[idx] = p;
}

// ---------------------------------------------------------------------------
// Launch
// ---------------------------------------------------------------------------
extern "C" void kernel_launch(void* const* d_in, const int* in_sizes, int n_in,
                              void* d_out, int out_size) {
    (void)in_sizes; (void)n_in; (void)out_size;
    const float* X     = (const float*)d_in[0];
    const float* genre = (const float*)d_in[1];
    const float* W1    = (const float*)d_in[2];
    const float* b1    = (const float*)d_in[3];
    const float* W2    = (const float*)d_in[4];
    const float* b2    = (const float*)d_in[5];
    const float* W3    = (const float*)d_in[6];
    const float* b3    = (const float*)d_in[7];
    const float* Wa    = (const float*)d_in[8];
    const float* ba    = (const float*)d_in[9];
    const float* Wagg  = (const float*)d_in[10];
    const float* bagg  = (const float*)d_in[11];
    float* out = (float*)d_out;

    float *w, *H3f;
    __half *Xh, *W1h, *W2h, *W3h, *Waggh, *H1h, *H2h, *Rh;
    int *counts, *idxArr, *pos;
    cudaGetSymbolAddress((void**)&w,      g_w);
    cudaGetSymbolAddress((void**)&Xh,     g_Xh);
    cudaGetSymbolAddress((void**)&W1h,    g_W1h);
    cudaGetSymbolAddress((void**)&W2h,    g_W2h);
    cudaGetSymbolAddress((void**)&W3h,    g_W3h);
    cudaGetSymbolAddress((void**)&Waggh,  g_Waggh);
    cudaGetSymbolAddress((void**)&H1h,    g_H1h);
    cudaGetSymbolAddress((void**)&H2h,    g_H2h);
    cudaGetSymbolAddress((void**)&H3f,    g_H3f);
    cudaGetSymbolAddress((void**)&Rh,     g_Rh);
    cudaGetSymbolAddress((void**)&counts, g_counts);
    cudaGetSymbolAddress((void**)&idxArr, g_idx);
    cudaGetSymbolAddress((void**)&pos,    g_pos);

    // Unconditional (idempotent, host-side, not captured) — no static guards.
    cudaFuncSetAttribute(gemm_fp16_kernel<1, 1, 1>,
                         cudaFuncAttributeMaxDynamicSharedMemorySize, GEMM_SMEM_BYTES);
    cudaFuncSetAttribute(gemm_fp16_kernel<1, 1, 2>,
                         cudaFuncAttributeMaxDynamicSharedMemorySize, GEMM_SMEM_BYTES);
    cudaFuncSetAttribute(gemm_fp16_kernel<0, 0, 2>,
                         cudaFuncAttributeMaxDynamicSharedMemorySize, GEMM_SMEM_BYTES);
    cudaFuncSetAttribute(gemm_fp16_kernel<1, 0, 3>,
                         cudaFuncAttributeMaxDynamicSharedMemorySize, GEMM_SMEM_BYTES);

    // 0) prep: cast X; transpose+cast weights to [N][K] fp16; compaction
    cast_x_kernel<<<512, 256>>>(X, Xh, BATCH * DIM / 4);
    transpose_cast_kernel<<<dim3(DIM / 32, HID2 / 32, NG), 256>>>(W1, W1h, DIM, HID2);
    transpose_cast_kernel<<<dim3(HID2 / 32, HID / 32, NG), 256>>>(W2, W2h, HID2, HID);
    transpose_cast_kernel<<<dim3(HID / 32, HID / 32, NG), 256>>>(W3, W3h, HID, HID);
    transpose_cast_kernel<<<dim3(DAGG / 32, DIM / 32, 1), 256>>>(Wagg, Waggh, DAGG, DIM);
    zero_kernel<<<288, 256>>>(counts, idxArr);
    compact_kernel<<<NG * BATCH / 256, 256>>>(genre, counts, idxArr, pos);

    // 1) attention weights (masked)
    attn_kernel<<<BATCH / 64, 256>>>(X, genre, Wa, ba, w);

    // 2) H1c = relu(gather(Xh) @ W1[g]^T + b1[g])  [compacted rows] -> fp16
    gemm_fp16_kernel<1, 1, 1><<<dim3(BATCH / BM, HID2 / BN, NG), 256, GEMM_SMEM_BYTES>>>(
        Xh, nullptr, W1h, b1, H1h,
        HID2, DIM, DIM,
        0LL, (long long)DIM * HID2, HID2, (long long)BATCH * HID2,
        idxArr, counts);

    // 3) H2c = relu(H1c @ W2[g]^T + b2[g]) -> fp16
    gemm_fp16_kernel<1, 1, 2><<<dim3(BATCH / BM, 1, NG), 256, GEMM_SMEM_BYTES>>>(
        H1h, nullptr, W2h, b2, H2h,
        HID, HID2, HID2,
        (long long)BATCH * HID2, (long long)HID2 * HID, HID, (long long)BATCH * HID,
        idxArr, counts);

    // 4) H3c = H2c @ W3[g]^T + b3[g] -> fp32
    gemm_fp16_kernel<0, 0, 2><<<dim3(BATCH / BM, 1, NG), 256, GEMM_SMEM_BYTES>>>(
        H2h, nullptr, W3h, b3, H3f,
        HID, HID, HID,
        (long long)BATCH * HID, (long long)HID * HID, HID, (long long)BATCH * HID,
        idxArr, counts);

    // 5) Rh = fp16( sum_g w .* H3c[pos] )
    reduce_kernel<<<(BATCH * 32) / 256, 256>>>(H3f, w, pos, Rh);

    // 6) out = relu([Xh, Rh] @ Wagg^T + bagg) -> fp32
    gemm_fp16_kernel<1, 0, 3><<<dim3(BATCH / BM, DIM / BN, 1), 256, GEMM_SMEM_BYTES>>>(
        Xh, Rh, Waggh, bagg, out,
        DIM, DAGG, DAGG,
        0LL, 0LL, 0LL, 0LL,
        idxArr, counts);
}

// round 10
// speedup vs baseline: 1.7850x; 1.0508x over previous
#include <cuda_runtime.h>
#include <cuda_fp16.h>
#include <cstdint>
#include <cstddef>

// Problem constants
#define BATCH   16384
#define DIM     512
#define HID     128     // H
#define HID2    256     // 2H
#define NG      18
#define DAGG    640     // D + H

// ---------------------------------------------------------------------------
// Scratch (device globals; allocation-free rule)
// ---------------------------------------------------------------------------
__device__ float  g_w[(size_t)BATCH * NG];                   // masked attention weights
__device__ __half g_Xh[(size_t)BATCH * DIM];                 // X cast to fp16
__device__ __half g_W1h[(size_t)NG * HID2 * DIM];            // weights n-major [g][N][K] fp16
__device__ __half g_W2h[(size_t)NG * HID * HID2];
__device__ __half g_W3h[(size_t)NG * HID * HID];
__device__ __half g_Waggh[(size_t)DIM * DAGG];               // [N=512][K=640]
__device__ __half g_H1h[(size_t)NG * BATCH * HID2];          // H1 compacted, fp16
__device__ __half g_H2h[(size_t)NG * BATCH * HID];           // H2 compacted, fp16
__device__ float  g_H3f[(size_t)NG * BATCH * HID];           // H3 compacted, fp32
__device__ __half g_Rh[(size_t)BATCH * HID];                 // refinements fp16
__device__ int    g_counts[32];                              // members per genre
__device__ int    g_idx[(size_t)NG * BATCH];                 // genre -> member rows
__device__ int    g_pos[(size_t)BATCH * NG];                 // (b,g) -> slot

// ---------------------------------------------------------------------------
// Helpers
// ---------------------------------------------------------------------------
__device__ __forceinline__ uint32_t smem_u32(const void* p) {
    uint32_t a;
    asm("{ .reg .u64 t; cvta.to.shared.u64 t, %1; cvt.u32.u64 %0, t; }" : "=r"(a) : "l"(p));
    return a;
}
__device__ __forceinline__ void cp_async16(uint32_t dst, const void* src) {
    asm volatile("cp.async.cg.shared.global [%0], [%1], 16;" :: "r"(dst), "l"(src) : "memory");
}
#define CP_COMMIT() asm volatile("cp.async.commit_group;" ::: "memory")
#define CP_WAIT(n)  asm volatile("cp.async.wait_group %0;" :: "n"(n) : "memory")

__device__ __forceinline__ void ldsm_x4(uint32_t addr, uint32_t* r) {
    asm volatile("ldmatrix.sync.aligned.m8n8.x4.shared.b16 {%0,%1,%2,%3}, [%4];"
        : "=r"(r[0]), "=r"(r[1]), "=r"(r[2]), "=r"(r[3]) : "r"(addr));
}

// fp16 MMA m16n8k16, fp32 accumulate
__device__ __forceinline__ void mma16(float* d, const uint32_t* a, const uint32_t* b) {
    asm volatile(
        "mma.sync.aligned.m16n8k16.row.col.f32.f16.f16.f32 "
        "{%0,%1,%2,%3}, {%4,%5,%6,%7}, {%8,%9}, {%0,%1,%2,%3};"
        : "+f"(d[0]), "+f"(d[1]), "+f"(d[2]), "+f"(d[3])
        : "r"(a[0]), "r"(a[1]), "r"(a[2]), "r"(a[3]), "r"(b[0]), "r"(b[1]));
}

// ---------------------------------------------------------------------------
// Prep: cast X to fp16 (grid-stride over float4 -> 4 halfs)
// ---------------------------------------------------------------------------
__global__ __launch_bounds__(256)
void cast_x_kernel(const float* __restrict__ in, __half* __restrict__ out, int n4) {
    int i = blockIdx.x * 256 + threadIdx.x;
    int stride = gridDim.x * 256;
    for (; i < n4; i += stride) {
        float4 v = ((const float4*)in)[i];
        __half2 h0 = __floats2half2_rn(v.x, v.y);
        __half2 h1 = __floats2half2_rn(v.z, v.w);
        uint2 p;
        p.x = *(uint32_t*)&h0;
        p.y = *(uint32_t*)&h1;
        ((uint2*)out)[i] = p;
    }
}

// ---------------------------------------------------------------------------
// Prep (fused): transpose + cast ALL weights fp32 [g][K][N] -> fp16 [g][N][K]
// Flat 32x32-tile index over W1 | W2 | W3 | Wagg.
//   W1:  18 * (512/32)*(256/32) = 2304 tiles
//   W2:  18 * (256/32)*(128/32) =  576   (cum 2880)
//   W3:  18 * (128/32)*(128/32) =  288   (cum 3168)
//   Wagg: 1 * (640/32)*(512/32) =  320   (cum 3488)
// ---------------------------------------------------------------------------
#define PREP_TILES 3488

__global__ __launch_bounds__(256)
void prep_weights_kernel(const float* __restrict__ W1, const float* __restrict__ W2,
                         const float* __restrict__ W3, const float* __restrict__ Wagg,
                         __half* __restrict__ W1h, __half* __restrict__ W2h,
                         __half* __restrict__ W3h, __half* __restrict__ Waggh) {
    __shared__ float t[32][33];
    int bz = blockIdx.x;
    const float* in;
    __half* out;
    int K, N, g, tt;
    if (bz < 2304)      { g = bz / 128;          tt = bz % 128; in = W1;   out = W1h;   K = DIM;  N = HID2; }
    else if (bz < 2880) { bz -= 2304; g = bz / 32; tt = bz % 32; in = W2;   out = W2h;   K = HID2; N = HID;  }
    else if (bz < 3168) { bz -= 2880; g = bz / 16; tt = bz % 16; in = W3;   out = W3h;   K = HID;  N = HID;  }
    else                { bz -= 3168; g = 0;       tt = bz;      in = Wagg; out = Waggh; K = DAGG; N = DIM;  }
    in  += (size_t)g * K * N;
    out += (size_t)g * K * N;
    int ntn = N / 32;
    int k0 = (tt / ntn) * 32;
    int n0 = (tt % ntn) * 32;
    int tx = threadIdx.x & 31, ty = threadIdx.x >> 5;   // 32 x 8
    #pragma unroll
    for (int i = 0; i < 4; i++) {
        int r = ty + i * 8;
        t[r][tx] = in[(size_t)(k0 + r) * N + n0 + tx];
    }
    __syncthreads();
    #pragma unroll
    for (int i = 0; i < 4; i++) {
        int r = ty + i * 8;
        out[(size_t)(n0 + r) * K + k0 + tx] = __float2half_rn(t[tx][r]);
    }
}

// ---------------------------------------------------------------------------
// Membership compaction
// ---------------------------------------------------------------------------
__global__ __launch_bounds__(256)
void zero_kernel(int* __restrict__ counts, int* __restrict__ idxArr) {
    int t = blockIdx.x * 256 + threadIdx.x;
    if (t < 32) counts[t] = 0;
    int n4 = NG * BATCH / 4;
    for (int i = t; i < n4; i += gridDim.x * 256)
        ((int4*)idxArr)[i] = make_int4(0, 0, 0, 0);
}

__global__ __launch_bounds__(256)
void compact_kernel(const float* __restrict__ genre, int* __restrict__ counts,
                    int* __restrict__ idxArr, int* __restrict__ pos) {
    int t = blockIdx.x * 256 + threadIdx.x;   // over NG * BATCH, g-major
    int g = t >> 14;                          // BATCH = 2^14
    int b = t & (BATCH - 1);
    float gv = genre[(size_t)b * NG + g];
    unsigned mask = __ballot_sync(0xffffffffu, gv > 0.f);
    int lane = threadIdx.x & 31;
    int base = 0;
    if (lane == 0 && mask) base = atomicAdd(&counts[g], __popc(mask));
    base = __shfl_sync(0xffffffffu, base, 0);
    if (gv > 0.f) {
        int slot = base + __popc(mask & ((1u << lane) - 1u));
        idxArr[(size_t)g * BATCH + slot] = b;
        pos[(size_t)b * NG + g] = slot;
    }
}

// ---------------------------------------------------------------------------
// Attention kernel (fp32): logits = X @ Wa + ba, softmax over G, mask
// ---------------------------------------------------------------------------
__global__ __launch_bounds__(256)
void attn_kernel(const float* __restrict__ X, const float* __restrict__ genre,
                 const float* __restrict__ Wa, const float* __restrict__ ba,
                 float* __restrict__ w) {
    __shared__ float Was[DIM * 19];
    __shared__ float bas[32];
    int tid = threadIdx.x;
    for (int i = tid; i < DIM * NG; i += 256) {
        int d = i / NG, g = i % NG;
        Was[d * 19 + g] = Wa[i];
    }
    if (tid < NG) bas[tid] = ba[tid];
    __syncthreads();

    int warp = tid >> 5, lane = tid & 31;
    for (int it = 0; it < 8; ++it) {
        int b = blockIdx.x * 64 + it * 8 + warp;
        float acc[NG];
        #pragma unroll
        for (int g = 0; g < NG; g++) acc[g] = 0.f;
        #pragma unroll
        for (int i = 0; i < 16; i++) {
            int d = 32 * i + lane;
            float xv = X[(size_t)b * DIM + d];
            const float* wrow = &Was[d * 19];
            #pragma unroll
            for (int g = 0; g < NG; g++) acc[g] += xv * wrow[g];
        }
        #pragma unroll
        for (int off = 16; off > 0; off >>= 1) {
            #pragma unroll
            for (int g = 0; g < NG; g++)
                acc[g] += __shfl_xor_sync(0xffffffffu, acc[g], off);
        }
        #pragma unroll
        for (int g = 0; g < NG; g++) acc[g] += bas[g];
        float mx = acc[0];
        #pragma unroll
        for (int g = 1; g < NG; g++) mx = fmaxf(mx, acc[g]);
        float s = 0.f, e_own = 0.f;
        #pragma unroll
        for (int g = 0; g < NG; g++) {
            float e = expf(acc[g] - mx);
            s += e;
            if (g == lane) e_own = e;
        }
        if (lane < NG) {
            float attn = e_own / s;
            float gv = genre[(size_t)b * NG + lane];
            w[(size_t)b * NG + lane] = (gv > 0.f) ? attn * gv : 0.f;
        }
    }
}

// ---------------------------------------------------------------------------
// fp16 GEMM (mma.sync m16n8k16 + ldmatrix fragments, cp.async double-buffered).
// A: [M][K] fp16 row-major (k-major). W: [N][K] fp16 n-major. fp32 accum.
// MODE: 1 = gather-A rows via idx + early-exit; 2 = dense + early-exit;
//       3 = concat [Xh | Rh] along K.
// OUTH: 1 = write fp16, 0 = write fp32.
// Block tile 128x128, K-chunk 64, 8 warps (4x2), warp tile 32x64.
// Fragments per kk-step: 2 A-ldmatrix.x4 + 4 B-ldmatrix.x4 + 16 HMMA.
// ---------------------------------------------------------------------------
#define BM  128
#define BN  128
#define BKH 64
#define LDH 72                      // half stride per row (64 + 8 pad); 144B
#define TSZ (128 * LDH)             // halves per tile
#define GEMM_SMEM_BYTES (4 * TSZ * 2)   // 2 stages x (A + B) x 2B

template<int ACT, int OUTH, int MODE>
__global__ __launch_bounds__(256, 2)
void gemm_fp16_kernel(const __half* __restrict__ A, const __half* __restrict__ Rp,
                      const __half* __restrict__ W, const float* __restrict__ bias,
                      void* __restrict__ Cv,
                      int N, int K, int lda,
                      long long sA, long long sW, long long sB, long long sC,
                      const int* __restrict__ idxArr, const int* __restrict__ counts) {
    int g = blockIdx.z;
    int m0 = blockIdx.x * BM;
    if (MODE == 1 || MODE == 2) {
        if (m0 >= counts[g]) return;
    }
    A    += (size_t)g * sA;
    W    += (size_t)g * sW;
    bias += (size_t)g * sB;
    const int* gidx = idxArr + (size_t)g * BATCH;

    extern __shared__ __half smh[];
    __half* As = smh;               // [2][TSZ]  [m][k] pad LDH
    __half* Bs = smh + 2 * TSZ;     // [2][TSZ]  [n][k] pad LDH
    uint32_t as_u = smem_u32(As);
    uint32_t bs_u = smem_u32(Bs);

    int tid  = threadIdx.x;
    int n0   = blockIdx.y * BN;
    int lane = tid & 31, warp = tid >> 5;
    int wm_base = (warp >> 1) * 32;
    int wn_base = (warp & 1) * 64;

    float acc[2][8][4];
    #pragma unroll
    for (int i = 0; i < 2; i++)
        #pragma unroll
        for (int j = 0; j < 8; j++)
            #pragma unroll
            for (int r = 0; r < 4; r++) acc[i][j][r] = 0.f;

    // Loaders: 32 rows per pass x 8 threads/row x 8 halfs (16B)
    int lr = tid >> 3, lc = (tid & 7) * 8;

    // Pre-resolve gathered row pointers for this thread's 4 A rows (MODE 1/2)
    const __half* arow_ptr[4];
    #pragma unroll
    for (int rr = 0; rr < 4; rr++) {
        int grow = m0 + lr + rr * 32;
        if (MODE == 1) {
            arow_ptr[rr] = A + (size_t)gidx[grow] * lda;
        } else {
            arow_ptr[rr] = A + (size_t)grow * lda;
        }
    }

    // ldmatrix per-lane byte offsets (relative to tile base, before kk shift)
    // A x4: M0 rows0-7/k0-7, M1 rows8-15/k0-7, M2 rows0-7/k8-15, M3 rows8-15/k8-15
    int lane8 = lane & 7;
    uint32_t a_off[2];
    #pragma unroll
    for (int wm = 0; wm < 2; wm++) {
        int row = wm_base + wm * 16 + lane8 + ((lane >> 3) & 1) * 8;
        int kof = (lane >> 4) * 8;
        a_off[wm] = (uint32_t)((row * LDH + kof) * 2);
    }
    // B x4: M0 n0-7/k0-7 (b0 lo), M1 n0-7/k8-15 (b1 lo), M2 n8-15/k0-7, M3 n8-15/k8-15
    uint32_t b_off[4];
    #pragma unroll
    for (int wnp = 0; wnp < 4; wnp++) {
        int row = wn_base + wnp * 16 + lane8 + (lane >> 4) * 8;
        int kof = ((lane >> 3) & 1) * 8;
        b_off[wnp] = (uint32_t)((row * LDH + kof) * 2);
    }

    int nchunks = K / BKH;

    auto stage = [&](int bsel, int k0) {
        uint32_t abase = as_u + (uint32_t)(bsel * TSZ) * 2;
        #pragma unroll
        for (int rr = 0; rr < 4; rr++) {
            int r = lr + rr * 32;
            int gcol = k0 + lc;
            const __half* src;
            if (MODE == 3) {
                int grow = m0 + r;
                src = (gcol < DIM) ? (A + (size_t)grow * DIM + gcol)
                                   : (Rp + (size_t)grow * HID + (gcol - DIM));
            } else {
                src = arow_ptr[rr] + gcol;
            }
            cp_async16(abase + (uint32_t)(r * LDH + lc) * 2, src);
        }
        uint32_t bbase = bs_u + (uint32_t)(bsel * TSZ) * 2;
        #pragma unroll
        for (int rr = 0; rr < 4; rr++) {
            int n = lr + rr * 32;
            cp_async16(bbase + (uint32_t)(n * LDH + lc) * 2,
                       W + (size_t)(n0 + n) * K + k0 + lc);
        }
    };

    stage(0, 0);
    CP_COMMIT();

    for (int c = 0; c < nchunks; c++) {
        int cur = c & 1;
        if (c + 1 < nchunks) {
            stage(cur ^ 1, (c + 1) * BKH);
            CP_COMMIT();
            CP_WAIT(1);
        } else {
            CP_WAIT(0);
        }
        __syncthreads();

        uint32_t ab = as_u + (uint32_t)(cur * TSZ) * 2;
        uint32_t bb = bs_u + (uint32_t)(cur * TSZ) * 2;

        #pragma unroll
        for (int kk = 0; kk < 4; kk++) {
            uint32_t kb = (uint32_t)(kk * 16 * 2);   // 16 halves per kk
            uint32_t af[2][4], bf[4][4];
            ldsm_x4(ab + a_off[0] + kb, af[0]);
            ldsm_x4(ab + a_off[1] + kb, af[1]);
            #pragma unroll
            for (int wnp = 0; wnp < 4; wnp++)
                ldsm_x4(bb + b_off[wnp] + kb, bf[wnp]);
            #pragma unroll
            for (int wm = 0; wm < 2; wm++)
                #pragma unroll
                for (int wnp = 0; wnp < 4; wnp++) {
                    mma16(acc[wm][2 * wnp],     af[wm], &bf[wnp][0]);
                    mma16(acc[wm][2 * wnp + 1], af[wm], &bf[wnp][2]);
                }
        }
        __syncthreads();
    }

    // ---- epilogue: + bias, optional relu, write fp16 or fp32 ----
    #pragma unroll
    for (int wm = 0; wm < 2; wm++) {
        int r0 = m0 + wm_base + wm * 16 + (lane >> 2);
        #pragma unroll
        for (int wn = 0; wn < 8; wn++) {
            int c0 = n0 + wn_base + wn * 8 + 2 * (lane & 3);
            float b0 = bias[c0], b1v = bias[c0 + 1];
            float v0 = acc[wm][wn][0] + b0;
            float v1 = acc[wm][wn][1] + b1v;
            float v2 = acc[wm][wn][2] + b0;
            float v3 = acc[wm][wn][3] + b1v;
            if (ACT) {
                v0 = fmaxf(v0, 0.f); v1 = fmaxf(v1, 0.f);
                v2 = fmaxf(v2, 0.f); v3 = fmaxf(v3, 0.f);
            }
            if (OUTH) {
                __half* C = (__half*)Cv + (size_t)g * sC;
                __half2 p0 = __floats2half2_rn(v0, v1);
                __half2 p1 = __floats2half2_rn(v2, v3);
                *(__half2*)(C + (size_t)r0 * N + c0)       = p0;
                *(__half2*)(C + (size_t)(r0 + 8) * N + c0) = p1;
            } else {
                float* C = (float*)Cv + (size_t)g * sC;
                *(float2*)(C + (size_t)r0 * N + c0)       = make_float2(v0, v1);
                *(float2*)(C + (size_t)(r0 + 8) * N + c0) = make_float2(v2, v3);
            }
        }
    }
}

// ---------------------------------------------------------------------------
// Weighted reduce (compacted): Rh[b,:] = fp16( sum_g w[b,g] * H3f[g, pos[b,g], :] )
// ---------------------------------------------------------------------------
__global__ __launch_bounds__(256)
void reduce_kernel(const float* __restrict__ H3, const float* __restrict__ w,
                   const int* __restrict__ pos, __half* __restrict__ Rh) {
    int idx = blockIdx.x * blockDim.x + threadIdx.x;   // over BATCH * 32 float4s
    int b = idx >> 5;
    int off = idx & 31;
    float4 r = make_float4(0.f, 0.f, 0.f, 0.f);
    const float4* H = (const float4*)H3;
    #pragma unroll
    for (int g = 0; g < NG; g++) {
        float wv = w[(size_t)b * NG + g];
        if (wv != 0.f) {
            int slot = pos[(size_t)b * NG + g];
            float4 h = H[((size_t)g * BATCH + slot) * 32 + off];
            r.x += wv * h.x; r.y += wv * h.y;
            r.z += wv * h.z; r.w += wv * h.w;
        }
    }
    __half2 p0 = __floats2half2_rn(r.x, r.y);
    __half2 p1 = __floats2half2_rn(r.z, r.w);
    uint2 p;
    p.x = *(uint32_t*)&p0;
    p.y = *(uint32_t*)&p1;
    ((uint2*)Rh)[idx] = p;
}

// ---------------------------------------------------------------------------
// Launch
// ---------------------------------------------------------------------------
extern "C" void kernel_launch(void* const* d_in, const int* in_sizes, int n_in,
                              void* d_out, int out_size) {
    (void)in_sizes; (void)n_in; (void)out_size;
    const float* X     = (const float*)d_in[0];
    const float* genre = (const float*)d_in[1];
    const float* W1    = (const float*)d_in[2];
    const float* b1    = (const float*)d_in[3];
    const float* W2    = (const float*)d_in[4];
    const float* b2    = (const float*)d_in[5];
    const float* W3    = (const float*)d_in[6];
    const float* b3    = (const float*)d_in[7];
    const float* Wa    = (const float*)d_in[8];
    const float* ba    = (const float*)d_in[9];
    const float* Wagg  = (const float*)d_in[10];
    const float* bagg  = (const float*)d_in[11];
    float* out = (float*)d_out;

    float *w, *H3f;
    __half *Xh, *W1h, *W2h, *W3h, *Waggh, *H1h, *H2h, *Rh;
    int *counts, *idxArr, *pos;
    cudaGetSymbolAddress((void**)&w,      g_w);
    cudaGetSymbolAddress((void**)&Xh,     g_Xh);
    cudaGetSymbolAddress((void**)&W1h,    g_W1h);
    cudaGetSymbolAddress((void**)&W2h,    g_W2h);
    cudaGetSymbolAddress((void**)&W3h,    g_W3h);
    cudaGetSymbolAddress((void**)&Waggh,  g_Waggh);
    cudaGetSymbolAddress((void**)&H1h,    g_H1h);
    cudaGetSymbolAddress((void**)&H2h,    g_H2h);
    cudaGetSymbolAddress((void**)&H3f,    g_H3f);
    cudaGetSymbolAddress((void**)&Rh,     g_Rh);
    cudaGetSymbolAddress((void**)&counts, g_counts);
    cudaGetSymbolAddress((void**)&idxArr, g_idx);
    cudaGetSymbolAddress((void**)&pos,    g_pos);

    // Unconditional (idempotent, host-side, not captured) — no static guards.
    cudaFuncSetAttribute(gemm_fp16_kernel<1, 1, 1>,
                         cudaFuncAttributeMaxDynamicSharedMemorySize, GEMM_SMEM_BYTES);
    cudaFuncSetAttribute(gemm_fp16_kernel<1, 1, 2>,
                         cudaFuncAttributeMaxDynamicSharedMemorySize, GEMM_SMEM_BYTES);
    cudaFuncSetAttribute(gemm_fp16_kernel<0, 0, 2>,
                         cudaFuncAttributeMaxDynamicSharedMemorySize, GEMM_SMEM_BYTES);
    cudaFuncSetAttribute(gemm_fp16_kernel<1, 0, 3>,
                         cudaFuncAttributeMaxDynamicSharedMemorySize, GEMM_SMEM_BYTES);

    // 0) prep: cast X; fused transpose+cast of all weights; compaction
    cast_x_kernel<<<512, 256>>>(X, Xh, BATCH * DIM / 4);
    prep_weights_kernel<<<PREP_TILES, 256>>>(W1, W2, W3, Wagg, W1h, W2h, W3h, Waggh);
    zero_kernel<<<288, 256>>>(counts, idxArr);
    compact_kernel<<<NG * BATCH / 256, 256>>>(genre, counts, idxArr, pos);

    // 1) attention weights (masked)
    attn_kernel<<<BATCH / 64, 256>>>(X, genre, Wa, ba, w);

    // 2) H1c = relu(gather(Xh) @ W1[g]^T + b1[g])  [compacted rows] -> fp16
    gemm_fp16_kernel<1, 1, 1><<<dim3(BATCH / BM, HID2 / BN, NG), 256, GEMM_SMEM_BYTES>>>(
        Xh, nullptr, W1h, b1, H1h,
        HID2, DIM, DIM,
        0LL, (long long)DIM * HID2, HID2, (long long)BATCH * HID2,
        idxArr, counts);

    // 3) H2c = relu(H1c @ W2[g]^T + b2[g]) -> fp16
    gemm_fp16_kernel<1, 1, 2><<<dim3(BATCH / BM, 1, NG), 256, GEMM_SMEM_BYTES>>>(
        H1h, nullptr, W2h, b2, H2h,
        HID, HID2, HID2,
        (long long)BATCH * HID2, (long long)HID2 * HID, HID, (long long)BATCH * HID,
        idxArr, counts);

    // 4) H3c = H2c @ W3[g]^T + b3[g] -> fp32
    gemm_fp16_kernel<0, 0, 2><<<dim3(BATCH / BM, 1, NG), 256, GEMM_SMEM_BYTES>>>(
        H2h, nullptr, W3h, b3, H3f,
        HID, HID, HID,
        (long long)BATCH * HID, (long long)HID * HID, HID, (long long)BATCH * HID,
        idxArr, counts);

    // 5) Rh = fp16( sum_g w .* H3c[pos] )
    reduce_kernel<<<(BATCH * 32) / 256, 256>>>(H3f, w, pos, Rh);

    // 6) out = relu([Xh, Rh] @ Wagg^T + bagg) -> fp32
    gemm_fp16_kernel<1, 0, 3><<<dim3(BATCH / BM, DIM / BN, 1), 256, GEMM_SMEM_BYTES>>>(
        Xh, Rh, Waggh, bagg, out,
        DIM, DAGG, DAGG,
        0LL, 0LL, 0LL, 0LL,
        idxArr, counts);
}

// round 12
// speedup vs baseline: 1.8806x; 1.0536x over previous
#include <cuda_runtime.h>
#include <cuda_fp16.h>
#include <cstdint>
#include <cstddef>

// Problem constants
#define BATCH   16384
#define DIM     512
#define HID     128     // H
#define HID2    256     // 2H
#define NG      18
#define DAGG    640     // D + H

// ---------------------------------------------------------------------------
// Scratch (device globals; allocation-free rule)
// ---------------------------------------------------------------------------
__device__ float  g_w[(size_t)BATCH * NG];                   // masked attention weights
__device__ __half g_Xh[(size_t)BATCH * DIM];                 // X cast to fp16
__device__ __half g_W1h[(size_t)NG * HID2 * DIM];            // weights n-major [g][N][K] fp16
__device__ __half g_W2h[(size_t)NG * HID * HID2];
__device__ __half g_W3h[(size_t)NG * HID * HID];
__device__ __half g_Waggh[(size_t)DIM * DAGG];               // [N=512][K=640]
__device__ __half g_H1h[(size_t)NG * BATCH * HID2];          // H1 compacted, fp16
__device__ float  g_H3f[(size_t)NG * BATCH * HID];           // H3 compacted, fp32
__device__ __half g_Rh[(size_t)BATCH * HID];                 // refinements fp16
__device__ int    g_counts[32];                              // members per genre
__device__ int    g_idx[(size_t)NG * BATCH];                 // genre -> member rows
__device__ int    g_pos[(size_t)BATCH * NG];                 // (b,g) -> slot

// ---------------------------------------------------------------------------
// Helpers
// ---------------------------------------------------------------------------
__device__ __forceinline__ uint32_t smem_u32(const void* p) {
    uint32_t a;
    asm("{ .reg .u64 t; cvta.to.shared.u64 t, %1; cvt.u32.u64 %0, t; }" : "=r"(a) : "l"(p));
    return a;
}
__device__ __forceinline__ void cp_async16(uint32_t dst, const void* src) {
    asm volatile("cp.async.cg.shared.global [%0], [%1], 16;" :: "r"(dst), "l"(src) : "memory");
}
#define CP_COMMIT() asm volatile("cp.async.commit_group;" ::: "memory")
#define CP_WAIT(n)  asm volatile("cp.async.wait_group %0;" :: "n"(n) : "memory")

__device__ __forceinline__ void ldsm_x4(uint32_t addr, uint32_t* r) {
    asm volatile("ldmatrix.sync.aligned.m8n8.x4.shared.b16 {%0,%1,%2,%3}, [%4];"
        : "=r"(r[0]), "=r"(r[1]), "=r"(r[2]), "=r"(r[3]) : "r"(addr));
}

// fp16 MMA m16n8k16, fp32 accumulate
__device__ __forceinline__ void mma16(float* d, const uint32_t* a, const uint32_t* b) {
    asm volatile(
        "mma.sync.aligned.m16n8k16.row.col.f32.f16.f16.f32 "
        "{%0,%1,%2,%3}, {%4,%5,%6,%7}, {%8,%9}, {%0,%1,%2,%3};"
        : "+f"(d[0]), "+f"(d[1]), "+f"(d[2]), "+f"(d[3])
        : "r"(a[0]), "r"(a[1]), "r"(a[2]), "r"(a[3]), "r"(b[0]), "r"(b[1]));
}

// ---------------------------------------------------------------------------
// Prep: cast X to fp16
// ---------------------------------------------------------------------------
__global__ __launch_bounds__(256)
void cast_x_kernel(const float* __restrict__ in, __half* __restrict__ out, int n4) {
    int i = blockIdx.x * 256 + threadIdx.x;
    int stride = gridDim.x * 256;
    for (; i < n4; i += stride) {
        float4 v = ((const float4*)in)[i];
        __half2 h0 = __floats2half2_rn(v.x, v.y);
        __half2 h1 = __floats2half2_rn(v.z, v.w);
        uint2 p;
        p.x = *(uint32_t*)&h0;
        p.y = *(uint32_t*)&h1;
        ((uint2*)out)[i] = p;
    }
}

// ---------------------------------------------------------------------------
// Prep (fused): transpose + cast ALL weights fp32 [g][K][N] -> fp16 [g][N][K]
// ---------------------------------------------------------------------------
#define PREP_TILES 3488

__global__ __launch_bounds__(256)
void prep_weights_kernel(const float* __restrict__ W1, const float* __restrict__ W2,
                         const float* __restrict__ W3, const float* __restrict__ Wagg,
                         __half* __restrict__ W1h, __half* __restrict__ W2h,
                         __half* __restrict__ W3h, __half* __restrict__ Waggh) {
    __shared__ float t[32][33];
    int bz = blockIdx.x;
    const float* in;
    __half* out;
    int K, N, g, tt;
    if (bz < 2304)      { g = bz / 128;          tt = bz % 128; in = W1;   out = W1h;   K = DIM;  N = HID2; }
    else if (bz < 2880) { bz -= 2304; g = bz / 32; tt = bz % 32; in = W2;   out = W2h;   K = HID2; N = HID;  }
    else if (bz < 3168) { bz -= 2880; g = bz / 16; tt = bz % 16; in = W3;   out = W3h;   K = HID;  N = HID;  }
    else                { bz -= 3168; g = 0;       tt = bz;      in = Wagg; out = Waggh; K = DAGG; N = DIM;  }
    in  += (size_t)g * K * N;
    out += (size_t)g * K * N;
    int ntn = N / 32;
    int k0 = (tt / ntn) * 32;
    int n0 = (tt % ntn) * 32;
    int tx = threadIdx.x & 31, ty = threadIdx.x >> 5;   // 32 x 8
    #pragma unroll
    for (int i = 0; i < 4; i++) {
        int r = ty + i * 8;
        t[r][tx] = in[(size_t)(k0 + r) * N + n0 + tx];
    }
    __syncthreads();
    #pragma unroll
    for (int i = 0; i < 4; i++) {
        int r = ty + i * 8;
        out[(size_t)(n0 + r) * K + k0 + tx] = __float2half_rn(t[tx][r]);
    }
}

// ---------------------------------------------------------------------------
// Membership compaction (counts cleared by tiny kernel; idx needs no zeroing
// because GEMM1 clamps padded rows to a valid slot)
// ---------------------------------------------------------------------------
__global__ void zero_counts_kernel(int* __restrict__ counts) {
    if (threadIdx.x < 32) counts[threadIdx.x] = 0;
}

__global__ __launch_bounds__(256)
void compact_kernel(const float* __restrict__ genre, int* __restrict__ counts,
                    int* __restrict__ idxArr, int* __restrict__ pos) {
    int t = blockIdx.x * 256 + threadIdx.x;   // over NG * BATCH, g-major
    int g = t >> 14;                          // BATCH = 2^14
    int b = t & (BATCH - 1);
    float gv = genre[(size_t)b * NG + g];
    unsigned mask = __ballot_sync(0xffffffffu, gv > 0.f);
    int lane = threadIdx.x & 31;
    int base = 0;
    if (lane == 0 && mask) base = atomicAdd(&counts[g], __popc(mask));
    base = __shfl_sync(0xffffffffu, base, 0);
    if (gv > 0.f) {
        int slot = base + __popc(mask & ((1u << lane) - 1u));
        idxArr[(size_t)g * BATCH + slot] = b;
        pos[(size_t)b * NG + g] = slot;
    }
}

// ---------------------------------------------------------------------------
// Attention kernel (fp32)
// ---------------------------------------------------------------------------
__global__ __launch_bounds__(256)
void attn_kernel(const float* __restrict__ X, const float* __restrict__ genre,
                 const float* __restrict__ Wa, const float* __restrict__ ba,
                 float* __restrict__ w) {
    __shared__ float Was[DIM * 19];
    __shared__ float bas[32];
    int tid = threadIdx.x;
    for (int i = tid; i < DIM * NG; i += 256) {
        int d = i / NG, g = i % NG;
        Was[d * 19 + g] = Wa[i];
    }
    if (tid < NG) bas[tid] = ba[tid];
    __syncthreads();

    int warp = tid >> 5, lane = tid & 31;
    for (int it = 0; it < 8; ++it) {
        int b = blockIdx.x * 64 + it * 8 + warp;
        float acc[NG];
        #pragma unroll
        for (int g = 0; g < NG; g++) acc[g] = 0.f;
        #pragma unroll
        for (int i = 0; i < 16; i++) {
            int d = 32 * i + lane;
            float xv = X[(size_t)b * DIM + d];
            const float* wrow = &Was[d * 19];
            #pragma unroll
            for (int g = 0; g < NG; g++) acc[g] += xv * wrow[g];
        }
        #pragma unroll
        for (int off = 16; off > 0; off >>= 1) {
            #pragma unroll
            for (int g = 0; g < NG; g++)
                acc[g] += __shfl_xor_sync(0xffffffffu, acc[g], off);
        }
        #pragma unroll
        for (int g = 0; g < NG; g++) acc[g] += bas[g];
        float mx = acc[0];
        #pragma unroll
        for (int g = 1; g < NG; g++) mx = fmaxf(mx, acc[g]);
        float s = 0.f, e_own = 0.f;
        #pragma unroll
        for (int g = 0; g < NG; g++) {
            float e = expf(acc[g] - mx);
            s += e;
            if (g == lane) e_own = e;
        }
        if (lane < NG) {
            float attn = e_own / s;
            float gv = genre[(size_t)b * NG + lane];
            w[(size_t)b * NG + lane] = (gv > 0.f) ? attn * gv : 0.f;
        }
    }
}

// ---------------------------------------------------------------------------
// Shared GEMM geometry
// ---------------------------------------------------------------------------
#define BM  128
#define BN  128
#define BKH 64
#define LDH 72                      // half stride per staged row (64 + 8 pad)
#define TSZ (128 * LDH)             // halves per staged tile
#define GEMM_SMEM_BYTES (4 * TSZ * 2)   // 2 stages x (A + B) x 2B

// ---------------------------------------------------------------------------
// fp16 GEMM (general): used for GEMM1 (MODE 1: gather-A + clamp) and the
// aggregation GEMM (MODE 3: concat [Xh|Rh]). OUTH: 1 fp16 out, 0 fp32 out.
// ---------------------------------------------------------------------------
template<int ACT, int OUTH, int MODE>
__global__ __launch_bounds__(256, 2)
void gemm_fp16_kernel(const __half* __restrict__ A, const __half* __restrict__ Rp,
                      const __half* __restrict__ W, const float* __restrict__ bias,
                      void* __restrict__ Cv,
                      int N, int K, int lda,
                      long long sA, long long sW, long long sB, long long sC,
                      const int* __restrict__ idxArr, const int* __restrict__ counts) {
    int g = blockIdx.z;
    int m0 = blockIdx.x * BM;
    int cnt = 0;
    if (MODE == 1) {
        cnt = counts[g];
        if (m0 >= cnt) return;
    }
    A    += (size_t)g * sA;
    W    += (size_t)g * sW;
    bias += (size_t)g * sB;
    const int* gidx = idxArr + (size_t)g * BATCH;

    extern __shared__ __half smh[];
    __half* As = smh;               // [2][TSZ]
    __half* Bs = smh + 2 * TSZ;     // [2][TSZ]
    uint32_t as_u = smem_u32(As);
    uint32_t bs_u = smem_u32(Bs);

    int tid  = threadIdx.x;
    int n0   = blockIdx.y * BN;
    int lane = tid & 31, warp = tid >> 5;
    int wm_base = (warp >> 1) * 32;
    int wn_base = (warp & 1) * 64;

    float acc[2][8][4];
    #pragma unroll
    for (int i = 0; i < 2; i++)
        #pragma unroll
        for (int j = 0; j < 8; j++)
            #pragma unroll
            for (int r = 0; r < 4; r++) acc[i][j][r] = 0.f;

    int lr = tid >> 3, lc = (tid & 7) * 8;

    const __half* arow_ptr[4];
    #pragma unroll
    for (int rr = 0; rr < 4; rr++) {
        int grow = m0 + lr + rr * 32;
        if (MODE == 1) {
            int cl = (grow < cnt) ? grow : (cnt - 1);   // clamp: idx beyond count unwritten
            arow_ptr[rr] = A + (size_t)gidx[cl] * lda;
        } else {
            arow_ptr[rr] = A + (size_t)grow * lda;
        }
    }

    int lane8 = lane & 7;
    uint32_t a_off[2];
    #pragma unroll
    for (int wm = 0; wm < 2; wm++) {
        int row = wm_base + wm * 16 + lane8 + ((lane >> 3) & 1) * 8;
        int kof = (lane >> 4) * 8;
        a_off[wm] = (uint32_t)((row * LDH + kof) * 2);
    }
    uint32_t b_off[4];
    #pragma unroll
    for (int wnp = 0; wnp < 4; wnp++) {
        int row = wn_base + wnp * 16 + lane8 + (lane >> 4) * 8;
        int kof = ((lane >> 3) & 1) * 8;
        b_off[wnp] = (uint32_t)((row * LDH + kof) * 2);
    }

    int nchunks = K / BKH;

    auto stage = [&](int bsel, int k0) {
        uint32_t abase = as_u + (uint32_t)(bsel * TSZ) * 2;
        #pragma unroll
        for (int rr = 0; rr < 4; rr++) {
            int r = lr + rr * 32;
            int gcol = k0 + lc;
            const __half* src;
            if (MODE == 3) {
                int grow = m0 + r;
                src = (gcol < DIM) ? (A + (size_t)grow * DIM + gcol)
                                   : (Rp + (size_t)grow * HID + (gcol - DIM));
            } else {
                src = arow_ptr[rr] + gcol;
            }
            cp_async16(abase + (uint32_t)(r * LDH + lc) * 2, src);
        }
        uint32_t bbase = bs_u + (uint32_t)(bsel * TSZ) * 2;
        #pragma unroll
        for (int rr = 0; rr < 4; rr++) {
            int n = lr + rr * 32;
            cp_async16(bbase + (uint32_t)(n * LDH + lc) * 2,
                       W + (size_t)(n0 + n) * K + k0 + lc);
        }
    };

    stage(0, 0);
    CP_COMMIT();

    for (int c = 0; c < nchunks; c++) {
        int cur = c & 1;
        if (c + 1 < nchunks) {
            stage(cur ^ 1, (c + 1) * BKH);
            CP_COMMIT();
            CP_WAIT(1);
        } else {
            CP_WAIT(0);
        }
        __syncthreads();

        uint32_t ab = as_u + (uint32_t)(cur * TSZ) * 2;
        uint32_t bb = bs_u + (uint32_t)(cur * TSZ) * 2;

        #pragma unroll
        for (int kk = 0; kk < 4; kk++) {
            uint32_t kb = (uint32_t)(kk * 16 * 2);
            uint32_t af[2][4], bf[4][4];
            ldsm_x4(ab + a_off[0] + kb, af[0]);
            ldsm_x4(ab + a_off[1] + kb, af[1]);
            #pragma unroll
            for (int wnp = 0; wnp < 4; wnp++)
                ldsm_x4(bb + b_off[wnp] + kb, bf[wnp]);
            #pragma unroll
            for (int wm = 0; wm < 2; wm++)
                #pragma unroll
                for (int wnp = 0; wnp < 4; wnp++) {
                    mma16(acc[wm][2 * wnp],     af[wm], &bf[wnp][0]);
                    mma16(acc[wm][2 * wnp + 1], af[wm], &bf[wnp][2]);
                }
        }
        __syncthreads();
    }

    #pragma unroll
    for (int wm = 0; wm < 2; wm++) {
        int r0 = m0 + wm_base + wm * 16 + (lane >> 2);
        #pragma unroll
        for (int wn = 0; wn < 8; wn++) {
            int c0 = n0 + wn_base + wn * 8 + 2 * (lane & 3);
            float b0 = bias[c0], b1v = bias[c0 + 1];
            float v0 = acc[wm][wn][0] + b0;
            float v1 = acc[wm][wn][1] + b1v;
            float v2 = acc[wm][wn][2] + b0;
            float v3 = acc[wm][wn][3] + b1v;
            if (ACT) {
                v0 = fmaxf(v0, 0.f); v1 = fmaxf(v1, 0.f);
                v2 = fmaxf(v2, 0.f); v3 = fmaxf(v3, 0.f);
            }
            if (OUTH) {
                __half* C = (__half*)Cv + (size_t)g * sC;
                __half2 p0 = __floats2half2_rn(v0, v1);
                __half2 p1 = __floats2half2_rn(v2, v3);
                *(__half2*)(C + (size_t)r0 * N + c0)       = p0;
                *(__half2*)(C + (size_t)(r0 + 8) * N + c0) = p1;
            } else {
                float* C = (float*)Cv + (size_t)g * sC;
                *(float2*)(C + (size_t)r0 * N + c0)       = make_float2(v0, v1);
                *(float2*)(C + (size_t)(r0 + 8) * N + c0) = make_float2(v2, v3);
            }
        }
    }
}

// ---------------------------------------------------------------------------
// Fused GEMM2+GEMM3:
//   phase 1: H2 = relu(H1c[m0:m0+128, :256] @ W2^T + b2) -> SMEM tile (fp16)
//   phase 2: H3 = H2tile @ W3^T + b3 -> global fp32
// FIX vs R11: mma_block now takes the A-fragment lane-offset array, so phase 2
// uses the LDH2-strided offsets (a2_off) for the H2 smem tile.
// ---------------------------------------------------------------------------
#define LDH2 136                                    // H2 tile stride (128 + 8)
#define H2TSZ (128 * LDH2)                          // 17408 halves
#define GEMM23_SMEM_BYTES (GEMM_SMEM_BYTES + H2TSZ * 2)   // 73728 + 34816

__global__ __launch_bounds__(256, 2)
void gemm23_fused_kernel(const __half* __restrict__ H1, const __half* __restrict__ W2,
                         const __half* __restrict__ W3,
                         const float* __restrict__ b2, const float* __restrict__ b3,
                         float* __restrict__ H3,
                         const int* __restrict__ counts) {
    int g = blockIdx.z;
    int m0 = blockIdx.x * BM;
    if (m0 >= counts[g]) return;
    H1 += (size_t)g * BATCH * HID2;
    W2 += (size_t)g * HID * HID2;
    W3 += (size_t)g * HID * HID;
    b2 += (size_t)g * HID;
    b3 += (size_t)g * HID;
    H3 += (size_t)g * BATCH * HID;

    extern __shared__ __half smh[];
    __half* As  = smh;                  // [2][TSZ]
    __half* Bs  = smh + 2 * TSZ;        // [2][TSZ]
    __half* H2s = smh + 4 * TSZ;        // [128][LDH2]
    uint32_t as_u  = smem_u32(As);
    uint32_t bs_u  = smem_u32(Bs);
    uint32_t h2_u  = smem_u32(H2s);

    int tid  = threadIdx.x;
    int lane = tid & 31, warp = tid >> 5;
    int wm_base = (warp >> 1) * 32;
    int wn_base = (warp & 1) * 64;

    float acc[2][8][4];
    #pragma unroll
    for (int i = 0; i < 2; i++)
        #pragma unroll
        for (int j = 0; j < 8; j++)
            #pragma unroll
            for (int r = 0; r < 4; r++) acc[i][j][r] = 0.f;

    int lr = tid >> 3, lc = (tid & 7) * 8;

    int lane8 = lane & 7;
    uint32_t a_off[2], a2_off[2];
    #pragma unroll
    for (int wm = 0; wm < 2; wm++) {
        int row = wm_base + wm * 16 + lane8 + ((lane >> 3) & 1) * 8;
        int kof = (lane >> 4) * 8;
        a_off[wm]  = (uint32_t)((row * LDH  + kof) * 2);
        a2_off[wm] = (uint32_t)((row * LDH2 + kof) * 2);
    }
    uint32_t b_off[4];
    #pragma unroll
    for (int wnp = 0; wnp < 4; wnp++) {
        int row = wn_base + wnp * 16 + lane8 + (lane >> 4) * 8;
        int kof = ((lane >> 3) & 1) * 8;
        b_off[wnp] = (uint32_t)((row * LDH + kof) * 2);
    }

    // phase-1 staging: A = H1 rows, B = W2 rows (both K=256, 4 chunks of 64)
    auto stage1 = [&](int bsel, int k0) {
        uint32_t abase = as_u + (uint32_t)(bsel * TSZ) * 2;
        #pragma unroll
        for (int rr = 0; rr < 4; rr++) {
            int r = lr + rr * 32;
            cp_async16(abase + (uint32_t)(r * LDH + lc) * 2,
                       H1 + (size_t)(m0 + r) * HID2 + k0 + lc);
        }
        uint32_t bbase = bs_u + (uint32_t)(bsel * TSZ) * 2;
        #pragma unroll
        for (int rr = 0; rr < 4; rr++) {
            int n = lr + rr * 32;
            cp_async16(bbase + (uint32_t)(n * LDH + lc) * 2,
                       W2 + (size_t)n * HID2 + k0 + lc);
        }
    };
    // W3 chunk staging into Bs[bsel] (K=128, chunks of 64)
    auto stage_w3 = [&](int bsel, int k0) {
        uint32_t bbase = bs_u + (uint32_t)(bsel * TSZ) * 2;
        #pragma unroll
        for (int rr = 0; rr < 4; rr++) {
            int n = lr + rr * 32;
            cp_async16(bbase + (uint32_t)(n * LDH + lc) * 2,
                       W3 + (size_t)n * HID + k0 + lc);
        }
    };

    auto mma_block = [&](uint32_t ab, uint32_t bb, const uint32_t* aoff) {
        #pragma unroll
        for (int kk = 0; kk < 4; kk++) {
            uint32_t kb = (uint32_t)(kk * 16 * 2);
            uint32_t af[2][4], bf[4][4];
            ldsm_x4(ab + aoff[0] + kb, af[0]);
            ldsm_x4(ab + aoff[1] + kb, af[1]);
            #pragma unroll
            for (int wnp = 0; wnp < 4; wnp++)
                ldsm_x4(bb + b_off[wnp] + kb, bf[wnp]);
            #pragma unroll
            for (int wm = 0; wm < 2; wm++)
                #pragma unroll
                for (int wnp = 0; wnp < 4; wnp++) {
                    mma16(acc[wm][2 * wnp],     af[wm], &bf[wnp][0]);
                    mma16(acc[wm][2 * wnp + 1], af[wm], &bf[wnp][2]);
                }
        }
    };

    // ---- phase 1 mainloop (4 chunks) ----
    stage1(0, 0);
    CP_COMMIT();
    for (int c = 0; c < 4; c++) {
        int cur = c & 1;
        if (c < 3) {
            stage1(cur ^ 1, (c + 1) * BKH);
            CP_COMMIT();
            CP_WAIT(1);
        } else {
            // last chunk (uses Bs[1]): prefetch W3 chunk0 into Bs[0] (free since c=2's sync)
            stage_w3(0, 0);
            CP_COMMIT();
            CP_WAIT(1);           // all phase-1 groups done; W3 group may remain in flight
        }
        __syncthreads();
        mma_block(as_u + (uint32_t)(cur * TSZ) * 2, bs_u + (uint32_t)(cur * TSZ) * 2, a_off);
        __syncthreads();
    }

    // ---- phase-1 epilogue: relu(acc + b2) -> H2 smem tile (fp16) ----
    #pragma unroll
    for (int wm = 0; wm < 2; wm++) {
        int r0 = wm_base + wm * 16 + (lane >> 2);
        #pragma unroll
        for (int wn = 0; wn < 8; wn++) {
            int c0 = wn_base + wn * 8 + 2 * (lane & 3);
            float b0 = b2[c0], b1v = b2[c0 + 1];
            float v0 = fmaxf(acc[wm][wn][0] + b0, 0.f);
            float v1 = fmaxf(acc[wm][wn][1] + b1v, 0.f);
            float v2 = fmaxf(acc[wm][wn][2] + b0, 0.f);
            float v3 = fmaxf(acc[wm][wn][3] + b1v, 0.f);
            *(__half2*)(H2s + r0 * LDH2 + c0)       = __floats2half2_rn(v0, v1);
            *(__half2*)(H2s + (r0 + 8) * LDH2 + c0) = __floats2half2_rn(v2, v3);
            // re-zero for phase 2
            acc[wm][wn][0] = 0.f; acc[wm][wn][1] = 0.f;
            acc[wm][wn][2] = 0.f; acc[wm][wn][3] = 0.f;
        }
    }
    // prefetch W3 chunk1 into Bs[1] (phase-1 mma on Bs[1] finished before epilogue)
    stage_w3(1, BKH);
    CP_COMMIT();
    CP_WAIT(0);
    __syncthreads();   // H2 tile + both W3 chunks visible to all warps

    // ---- phase 2: H3 = H2tile @ W3^T (2 chunks, no syncs needed) ----
    #pragma unroll
    for (int c2 = 0; c2 < 2; c2++) {
        uint32_t ab = h2_u + (uint32_t)(c2 * BKH) * 2;   // advance K within H2 tile
        uint32_t bb = bs_u + (uint32_t)(c2 * TSZ) * 2;
        mma_block(ab, bb, a2_off);
    }

    // ---- phase-2 epilogue: acc + b3 -> H3 global (fp32) ----
    #pragma unroll
    for (int wm = 0; wm < 2; wm++) {
        int r0 = wm_base + wm * 16 + (lane >> 2);
        #pragma unroll
        for (int wn = 0; wn < 8; wn++) {
            int c0 = wn_base + wn * 8 + 2 * (lane & 3);
            float b0 = b3[c0], b1v = b3[c0 + 1];
            float v0 = acc[wm][wn][0] + b0;
            float v1 = acc[wm][wn][1] + b1v;
            float v2 = acc[wm][wn][2] + b0;
            float v3 = acc[wm][wn][3] + b1v;
            *(float2*)(H3 + (size_t)(m0 + r0) * HID + c0)       = make_float2(v0, v1);
            *(float2*)(H3 + (size_t)(m0 + r0 + 8) * HID + c0)   = make_float2(v2, v3);
        }
    }
}

// ---------------------------------------------------------------------------
// Weighted reduce (compacted): Rh[b,:] = fp16( sum_g w[b,g] * H3f[g, pos[b,g], :] )
// ---------------------------------------------------------------------------
__global__ __launch_bounds__(256)
void reduce_kernel(const float* __restrict__ H3, const float* __restrict__ w,
                   const int* __restrict__ pos, __half* __restrict__ Rh) {
    int idx = blockIdx.x * blockDim.x + threadIdx.x;
    int b = idx >> 5;
    int off = idx & 31;
    float4 r = make_float4(0.f, 0.f, 0.f, 0.f);
    const float4* H = (const float4*)H3;
    #pragma unroll
    for (int g = 0; g < NG; g++) {
        float wv = w[(size_t)b * NG + g];
        if (wv != 0.f) {
            int slot = pos[(size_t)b * NG + g];
            float4 h = H[((size_t)g * BATCH + slot) * 32 + off];
            r.x += wv * h.x; r.y += wv * h.y;
            r.z += wv * h.z; r.w += wv * h.w;
        }
    }
    __half2 p0 = __floats2half2_rn(r.x, r.y);
    __half2 p1 = __floats2half2_rn(r.z, r.w);
    uint2 p;
    p.x = *(uint32_t*)&p0;
    p.y = *(uint32_t*)&p1;
    ((uint2*)Rh)[idx] = p;
}

// ---------------------------------------------------------------------------
// Launch
// ---------------------------------------------------------------------------
extern "C" void kernel_launch(void* const* d_in, const int* in_sizes, int n_in,
                              void* d_out, int out_size) {
    (void)in_sizes; (void)n_in; (void)out_size;
    const float* X     = (const float*)d_in[0];
    const float* genre = (const float*)d_in[1];
    const float* W1    = (const float*)d_in[2];
    const float* b1    = (const float*)d_in[3];
    const float* W2    = (const float*)d_in[4];
    const float* b2    = (const float*)d_in[5];
    const float* W3    = (const float*)d_in[6];
    const float* b3    = (const float*)d_in[7];
    const float* Wa    = (const float*)d_in[8];
    const float* ba    = (const float*)d_in[9];
    const float* Wagg  = (const float*)d_in[10];
    const float* bagg  = (const float*)d_in[11];
    float* out = (float*)d_out;

    float *w, *H3f;
    __half *Xh, *W1h, *W2h, *W3h, *Waggh, *H1h, *Rh;
    int *counts, *idxArr, *pos;
    cudaGetSymbolAddress((void**)&w,      g_w);
    cudaGetSymbolAddress((void**)&Xh,     g_Xh);
    cudaGetSymbolAddress((void**)&W1h,    g_W1h);
    cudaGetSymbolAddress((void**)&W2h,    g_W2h);
    cudaGetSymbolAddress((void**)&W3h,    g_W3h);
    cudaGetSymbolAddress((void**)&Waggh,  g_Waggh);
    cudaGetSymbolAddress((void**)&H1h,    g_H1h);
    cudaGetSymbolAddress((void**)&H3f,    g_H3f);
    cudaGetSymbolAddress((void**)&Rh,     g_Rh);
    cudaGetSymbolAddress((void**)&counts, g_counts);
    cudaGetSymbolAddress((void**)&idxArr, g_idx);
    cudaGetSymbolAddress((void**)&pos,    g_pos);

    // Unconditional (idempotent, host-side, not captured) — no static guards.
    cudaFuncSetAttribute(gemm_fp16_kernel<1, 1, 1>,
                         cudaFuncAttributeMaxDynamicSharedMemorySize, GEMM_SMEM_BYTES);
    cudaFuncSetAttribute(gemm_fp16_kernel<1, 0, 3>,
                         cudaFuncAttributeMaxDynamicSharedMemorySize, GEMM_SMEM_BYTES);
    cudaFuncSetAttribute(gemm23_fused_kernel,
                         cudaFuncAttributeMaxDynamicSharedMemorySize, GEMM23_SMEM_BYTES);

    // 0) prep
    cast_x_kernel<<<512, 256>>>(X, Xh, BATCH * DIM / 4);
    prep_weights_kernel<<<PREP_TILES, 256>>>(W1, W2, W3, Wagg, W1h, W2h, W3h, Waggh);
    zero_counts_kernel<<<1, 32>>>(counts);
    compact_kernel<<<NG * BATCH / 256, 256>>>(genre, counts, idxArr, pos);

    // 1) attention weights (masked)
    attn_kernel<<<BATCH / 64, 256>>>(X, genre, Wa, ba, w);

    // 2) H1c = relu(gather(Xh) @ W1[g]^T + b1[g]) -> fp16
    gemm_fp16_kernel<1, 1, 1><<<dim3(BATCH / BM, HID2 / BN, NG), 256, GEMM_SMEM_BYTES>>>(
        Xh, nullptr, W1h, b1, H1h,
        HID2, DIM, DIM,
        0LL, (long long)DIM * HID2, HID2, (long long)BATCH * HID2,
        idxArr, counts);

    // 3+4) fused: H3c = (relu(H1c @ W2^T + b2)) @ W3^T + b3 -> fp32
    gemm23_fused_kernel<<<dim3(BATCH / BM, 1, NG), 256, GEMM23_SMEM_BYTES>>>(
        H1h, W2h, W3h, b2, b3, H3f, counts);

    // 5) Rh = fp16( sum_g w .* H3c[pos] )
    reduce_kernel<<<(BATCH * 32) / 256, 256>>>(H3f, w, pos, Rh);

    // 6) out = relu([Xh, Rh] @ Wagg^T + bagg) -> fp32
    gemm_fp16_kernel<1, 0, 3><<<dim3(BATCH / BM, DIM / BN, 1), 256, GEMM_SMEM_BYTES>>>(
        Xh, Rh, Waggh, bagg, out,
        DIM, DAGG, DAGG,
        0LL, 0LL, 0LL, 0LL,
        idxArr, counts);
}

// round 13
// speedup vs baseline: 1.9493x; 1.0365x over previous
#include <cuda_runtime.h>
#include <cuda_fp16.h>
#include <cstdint>
#include <cstddef>

// Problem constants
#define BATCH   16384
#define DIM     512
#define HID     128     // H
#define HID2    256     // 2H
#define NG      18
#define DAGG    640     // D + H

// ---------------------------------------------------------------------------
// Scratch (device globals; allocation-free rule)
// ---------------------------------------------------------------------------
__device__ float  g_w[(size_t)BATCH * NG];                   // masked attention weights
__device__ __half g_Xh[(size_t)BATCH * DIM];                 // X cast to fp16
__device__ __half g_W1h[(size_t)NG * HID2 * DIM];            // weights n-major [g][N][K] fp16
__device__ __half g_W2h[(size_t)NG * HID * HID2];
__device__ __half g_W3h[(size_t)NG * HID * HID];
__device__ __half g_Waggh[(size_t)DIM * DAGG];               // [N=512][K=640]
__device__ __half g_H1h[(size_t)NG * BATCH * HID2];          // H1 compacted, fp16
__device__ float  g_H3f[(size_t)NG * BATCH * HID];           // H3 compacted, fp32
__device__ __half g_Rh[(size_t)BATCH * HID];                 // refinements fp16
__device__ int    g_counts[32];                              // members per genre
__device__ int    g_idx[(size_t)NG * BATCH];                 // genre -> member rows
__device__ int    g_pos[(size_t)BATCH * NG];                 // (b,g) -> slot

// ---------------------------------------------------------------------------
// Helpers
// ---------------------------------------------------------------------------
__device__ __forceinline__ uint32_t smem_u32(const void* p) {
    uint32_t a;
    asm("{ .reg .u64 t; cvta.to.shared.u64 t, %1; cvt.u32.u64 %0, t; }" : "=r"(a) : "l"(p));
    return a;
}
__device__ __forceinline__ void cp_async16(uint32_t dst, const void* src) {
    asm volatile("cp.async.cg.shared.global [%0], [%1], 16;" :: "r"(dst), "l"(src) : "memory");
}
#define CP_COMMIT() asm volatile("cp.async.commit_group;" ::: "memory")
#define CP_WAIT(n)  asm volatile("cp.async.wait_group %0;" :: "n"(n) : "memory")

__device__ __forceinline__ void ldsm_x4(uint32_t addr, uint32_t* r) {
    asm volatile("ldmatrix.sync.aligned.m8n8.x4.shared.b16 {%0,%1,%2,%3}, [%4];"
        : "=r"(r[0]), "=r"(r[1]), "=r"(r[2]), "=r"(r[3]) : "r"(addr));
}

// fp16 MMA m16n8k16, fp32 accumulate
__device__ __forceinline__ void mma16(float* d, const uint32_t* a, const uint32_t* b) {
    asm volatile(
        "mma.sync.aligned.m16n8k16.row.col.f32.f16.f16.f32 "
        "{%0,%1,%2,%3}, {%4,%5,%6,%7}, {%8,%9}, {%0,%1,%2,%3};"
        : "+f"(d[0]), "+f"(d[1]), "+f"(d[2]), "+f"(d[3])
        : "r"(a[0]), "r"(a[1]), "r"(a[2]), "r"(a[3]), "r"(b[0]), "r"(b[1]));
}

// ---------------------------------------------------------------------------
// Prep (fused): weight transpose+cast tiles, X cast, counts zeroing.
//   blocks [0, 3488): 32x32 transpose+cast tiles over W1|W2|W3|Wagg
//   blocks [3488, 4000): grid-stride fp32->fp16 cast of X; block 3488 also
//                        zeroes counts.
// ---------------------------------------------------------------------------
#define PREP_TILES 3488
#define PREP_CAST  512
#define PREP_TOTAL (PREP_TILES + PREP_CAST)

__global__ __launch_bounds__(256)
void prep_kernel(const float* __restrict__ W1, const float* __restrict__ W2,
                 const float* __restrict__ W3, const float* __restrict__ Wagg,
                 const float* __restrict__ X,
                 __half* __restrict__ W1h, __half* __restrict__ W2h,
                 __half* __restrict__ W3h, __half* __restrict__ Waggh,
                 __half* __restrict__ Xh, int* __restrict__ counts) {
    int bz = blockIdx.x;
    int tid = threadIdx.x;

    if (bz >= PREP_TILES) {
        // X cast region
        int local = bz - PREP_TILES;
        if (local == 0 && tid < 32) counts[tid] = 0;
        int n4 = BATCH * DIM / 4;
        for (int i = local * 256 + tid; i < n4; i += PREP_CAST * 256) {
            float4 v = ((const float4*)X)[i];
            __half2 h0 = __floats2half2_rn(v.x, v.y);
            __half2 h1 = __floats2half2_rn(v.z, v.w);
            uint2 p;
            p.x = *(uint32_t*)&h0;
            p.y = *(uint32_t*)&h1;
            ((uint2*)Xh)[i] = p;
        }
        return;
    }

    __shared__ float t[32][33];
    const float* in;
    __half* out;
    int K, N, g, tt;
    if (bz < 2304)      { g = bz / 128;          tt = bz % 128; in = W1;   out = W1h;   K = DIM;  N = HID2; }
    else if (bz < 2880) { bz -= 2304; g = bz / 32; tt = bz % 32; in = W2;   out = W2h;   K = HID2; N = HID;  }
    else if (bz < 3168) { bz -= 2880; g = bz / 16; tt = bz % 16; in = W3;   out = W3h;   K = HID;  N = HID;  }
    else                { bz -= 3168; g = 0;       tt = bz;      in = Wagg; out = Waggh; K = DAGG; N = DIM;  }
    in  += (size_t)g * K * N;
    out += (size_t)g * K * N;
    int ntn = N / 32;
    int k0 = (tt / ntn) * 32;
    int n0 = (tt % ntn) * 32;
    int tx = tid & 31, ty = tid >> 5;   // 32 x 8
    #pragma unroll
    for (int i = 0; i < 4; i++) {
        int r = ty + i * 8;
        t[r][tx] = in[(size_t)(k0 + r) * N + n0 + tx];
    }
    __syncthreads();
    #pragma unroll
    for (int i = 0; i < 4; i++) {
        int r = ty + i * 8;
        out[(size_t)(n0 + r) * K + k0 + tx] = __float2half_rn(t[tx][r]);
    }
}

// ---------------------------------------------------------------------------
// Membership compaction, coalesced:
// block = 256 consecutive b. Load genre tile to smem (coalesced), one
// atomicAdd per (block, g), contiguous idx slots, pos staged in smem and
// written coalesced.
// ---------------------------------------------------------------------------
__global__ __launch_bounds__(256)
void compact_kernel(const float* __restrict__ genre, int* __restrict__ counts,
                    int* __restrict__ idxArr, int* __restrict__ pos) {
    __shared__ float gt[256][19];
    __shared__ int   ps[256][19];
    int b0 = blockIdx.x * 256;
    int tid = threadIdx.x;
    for (int i = tid; i < 256 * NG; i += 256) {
        gt[i / NG][i % NG] = genre[(size_t)b0 * NG + i];
    }
    __syncthreads();
    int warp = tid >> 5, lane = tid & 31;
    for (int g = warp; g < NG; g += 8) {
        unsigned masks[8];
        int total = 0;
        #pragma unroll
        for (int s = 0; s < 8; s++) {
            float v = gt[s * 32 + lane][g];
            masks[s] = __ballot_sync(0xffffffffu, v > 0.f);
            total += __popc(masks[s]);
        }
        int base = 0;
        if (lane == 0) base = atomicAdd(&counts[g], total);
        base = __shfl_sync(0xffffffffu, base, 0);
        int run = 0;
        #pragma unroll
        for (int s = 0; s < 8; s++) {
            unsigned m = masks[s];
            if (m & (1u << lane)) {
                int slot = base + run + __popc(m & ((1u << lane) - 1u));
                idxArr[(size_t)g * BATCH + slot] = b0 + s * 32 + lane;
                ps[s * 32 + lane][g] = slot;
            }
            run += __popc(m);
        }
    }
    __syncthreads();
    for (int i = tid; i < 256 * NG; i += 256) {
        pos[(size_t)b0 * NG + i] = ps[i / NG][i % NG];
    }
}

// ---------------------------------------------------------------------------
// Attention kernel (fp32)
// ---------------------------------------------------------------------------
__global__ __launch_bounds__(256)
void attn_kernel(const float* __restrict__ X, const float* __restrict__ genre,
                 const float* __restrict__ Wa, const float* __restrict__ ba,
                 float* __restrict__ w) {
    __shared__ float Was[DIM * 19];
    __shared__ float bas[32];
    int tid = threadIdx.x;
    for (int i = tid; i < DIM * NG; i += 256) {
        int d = i / NG, g = i % NG;
        Was[d * 19 + g] = Wa[i];
    }
    if (tid < NG) bas[tid] = ba[tid];
    __syncthreads();

    int warp = tid >> 5, lane = tid & 31;
    for (int it = 0; it < 8; ++it) {
        int b = blockIdx.x * 64 + it * 8 + warp;
        float acc[NG];
        #pragma unroll
        for (int g = 0; g < NG; g++) acc[g] = 0.f;
        #pragma unroll
        for (int i = 0; i < 16; i++) {
            int d = 32 * i + lane;
            float xv = X[(size_t)b * DIM + d];
            const float* wrow = &Was[d * 19];
            #pragma unroll
            for (int g = 0; g < NG; g++) acc[g] += xv * wrow[g];
        }
        #pragma unroll
        for (int off = 16; off > 0; off >>= 1) {
            #pragma unroll
            for (int g = 0; g < NG; g++)
                acc[g] += __shfl_xor_sync(0xffffffffu, acc[g], off);
        }
        #pragma unroll
        for (int g = 0; g < NG; g++) acc[g] += bas[g];
        float mx = acc[0];
        #pragma unroll
        for (int g = 1; g < NG; g++) mx = fmaxf(mx, acc[g]);
        float s = 0.f, e_own = 0.f;
        #pragma unroll
        for (int g = 0; g < NG; g++) {
            float e = expf(acc[g] - mx);
            s += e;
            if (g == lane) e_own = e;
        }
        if (lane < NG) {
            float attn = e_own / s;
            float gv = genre[(size_t)b * NG + lane];
            w[(size_t)b * NG + lane] = (gv > 0.f) ? attn * gv : 0.f;
        }
    }
}

// ---------------------------------------------------------------------------
// Shared GEMM geometry
// ---------------------------------------------------------------------------
#define BM  128
#define BN  128
#define BKH 64
#define LDH 72                      // half stride per staged row (64 + 8 pad)
#define TSZ (128 * LDH)             // halves per staged tile
#define NSTAGE 3
#define GEMM_SMEM_BYTES (2 * NSTAGE * TSZ * 2)   // 3 stages x (A + B) x 2B = 110592

// ---------------------------------------------------------------------------
// fp16 GEMM (general, 3-stage pipeline, one barrier per chunk):
// MODE 1: gather-A rows via idx + clamp + early-exit; MODE 3: concat [Xh|Rh].
// OUTH: 1 fp16 out, 0 fp32 out.
// ---------------------------------------------------------------------------
template<int ACT, int OUTH, int MODE>
__global__ __launch_bounds__(256, 2)
void gemm_fp16_kernel(const __half* __restrict__ A, const __half* __restrict__ Rp,
                      const __half* __restrict__ W, const float* __restrict__ bias,
                      void* __restrict__ Cv,
                      int N, int K, int lda,
                      long long sA, long long sW, long long sB, long long sC,
                      const int* __restrict__ idxArr, const int* __restrict__ counts) {
    int g = blockIdx.z;
    int m0 = blockIdx.x * BM;
    int cnt = 0;
    if (MODE == 1) {
        cnt = counts[g];
        if (m0 >= cnt) return;
    }
    A    += (size_t)g * sA;
    W    += (size_t)g * sW;
    bias += (size_t)g * sB;
    const int* gidx = idxArr + (size_t)g * BATCH;

    extern __shared__ __half smh[];
    __half* As = smh;                       // [NSTAGE][TSZ]
    __half* Bs = smh + NSTAGE * TSZ;        // [NSTAGE][TSZ]
    uint32_t as_u = smem_u32(As);
    uint32_t bs_u = smem_u32(Bs);

    int tid  = threadIdx.x;
    int n0   = blockIdx.y * BN;
    int lane = tid & 31, warp = tid >> 5;
    int wm_base = (warp >> 1) * 32;
    int wn_base = (warp & 1) * 64;

    float acc[2][8][4];
    #pragma unroll
    for (int i = 0; i < 2; i++)
        #pragma unroll
        for (int j = 0; j < 8; j++)
            #pragma unroll
            for (int r = 0; r < 4; r++) acc[i][j][r] = 0.f;

    int lr = tid >> 3, lc = (tid & 7) * 8;

    const __half* arow_ptr[4];
    #pragma unroll
    for (int rr = 0; rr < 4; rr++) {
        int grow = m0 + lr + rr * 32;
        if (MODE == 1) {
            int cl = (grow < cnt) ? grow : (cnt - 1);   // clamp: padded rows never consumed
            arow_ptr[rr] = A + (size_t)gidx[cl] * lda;
        } else {
            arow_ptr[rr] = A + (size_t)grow * lda;
        }
    }

    int lane8 = lane & 7;
    uint32_t a_off[2];
    #pragma unroll
    for (int wm = 0; wm < 2; wm++) {
        int row = wm_base + wm * 16 + lane8 + ((lane >> 3) & 1) * 8;
        int kof = (lane >> 4) * 8;
        a_off[wm] = (uint32_t)((row * LDH + kof) * 2);
    }
    uint32_t b_off[4];
    #pragma unroll
    for (int wnp = 0; wnp < 4; wnp++) {
        int row = wn_base + wnp * 16 + lane8 + (lane >> 4) * 8;
        int kof = ((lane >> 3) & 1) * 8;
        b_off[wnp] = (uint32_t)((row * LDH + kof) * 2);
    }

    int nchunks = K / BKH;

    auto stage = [&](int bsel, int k0) {
        uint32_t abase = as_u + (uint32_t)(bsel * TSZ) * 2;
        #pragma unroll
        for (int rr = 0; rr < 4; rr++) {
            int r = lr + rr * 32;
            int gcol = k0 + lc;
            const __half* src;
            if (MODE == 3) {
                int grow = m0 + r;
                src = (gcol < DIM) ? (A + (size_t)grow * DIM + gcol)
                                   : (Rp + (size_t)grow * HID + (gcol - DIM));
            } else {
                src = arow_ptr[rr] + gcol;
            }
            cp_async16(abase + (uint32_t)(r * LDH + lc) * 2, src);
        }
        uint32_t bbase = bs_u + (uint32_t)(bsel * TSZ) * 2;
        #pragma unroll
        for (int rr = 0; rr < 4; rr++) {
            int n = lr + rr * 32;
            cp_async16(bbase + (uint32_t)(n * LDH + lc) * 2,
                       W + (size_t)(n0 + n) * K + k0 + lc);
        }
    };

    // 3-stage prologue: chunks 0 and 1 in flight
    stage(0, 0);
    CP_COMMIT();
    if (nchunks > 1) {
        stage(1, BKH);
        CP_COMMIT();
    }

    for (int c = 0; c < nchunks; c++) {
        if (c + 1 < nchunks) { CP_WAIT(1); } else { CP_WAIT(0); }
        __syncthreads();
        if (c + 2 < nchunks) {
            stage((c + 2) % NSTAGE, (c + 2) * BKH);
            CP_COMMIT();
        }
        int cur = c % NSTAGE;
        uint32_t ab = as_u + (uint32_t)(cur * TSZ) * 2;
        uint32_t bb = bs_u + (uint32_t)(cur * TSZ) * 2;

        #pragma unroll
        for (int kk = 0; kk < 4; kk++) {
            uint32_t kb = (uint32_t)(kk * 16 * 2);
            uint32_t af[2][4], bf[4][4];
            ldsm_x4(ab + a_off[0] + kb, af[0]);
            ldsm_x4(ab + a_off[1] + kb, af[1]);
            #pragma unroll
            for (int wnp = 0; wnp < 4; wnp++)
                ldsm_x4(bb + b_off[wnp] + kb, bf[wnp]);
            #pragma unroll
            for (int wm = 0; wm < 2; wm++)
                #pragma unroll
                for (int wnp = 0; wnp < 4; wnp++) {
                    mma16(acc[wm][2 * wnp],     af[wm], &bf[wnp][0]);
                    mma16(acc[wm][2 * wnp + 1], af[wm], &bf[wnp][2]);
                }
        }
    }

    #pragma unroll
    for (int wm = 0; wm < 2; wm++) {
        int r0 = m0 + wm_base + wm * 16 + (lane >> 2);
        #pragma unroll
        for (int wn = 0; wn < 8; wn++) {
            int c0 = n0 + wn_base + wn * 8 + 2 * (lane & 3);
            float b0 = bias[c0], b1v = bias[c0 + 1];
            float v0 = acc[wm][wn][0] + b0;
            float v1 = acc[wm][wn][1] + b1v;
            float v2 = acc[wm][wn][2] + b0;
            float v3 = acc[wm][wn][3] + b1v;
            if (ACT) {
                v0 = fmaxf(v0, 0.f); v1 = fmaxf(v1, 0.f);
                v2 = fmaxf(v2, 0.f); v3 = fmaxf(v3, 0.f);
            }
            if (OUTH) {
                __half* C = (__half*)Cv + (size_t)g * sC;
                __half2 p0 = __floats2half2_rn(v0, v1);
                __half2 p1 = __floats2half2_rn(v2, v3);
                *(__half2*)(C + (size_t)r0 * N + c0)       = p0;
                *(__half2*)(C + (size_t)(r0 + 8) * N + c0) = p1;
            } else {
                float* C = (float*)Cv + (size_t)g * sC;
                *(float2*)(C + (size_t)r0 * N + c0)       = make_float2(v0, v1);
                *(float2*)(C + (size_t)(r0 + 8) * N + c0) = make_float2(v2, v3);
            }
        }
    }
}

// ---------------------------------------------------------------------------
// Fused GEMM2+GEMM3 (unchanged from R12, passing):
//   phase 1: H2 = relu(H1c @ W2^T + b2) -> SMEM tile (fp16)
//   phase 2: H3 = H2tile @ W3^T + b3 -> global fp32
// ---------------------------------------------------------------------------
#define LDH2 136
#define H2TSZ (128 * LDH2)
#define G23_STAGE_BYTES (4 * TSZ * 2)                       // 2-stage A+B = 73728
#define GEMM23_SMEM_BYTES (G23_STAGE_BYTES + H2TSZ * 2)     // + H2 tile

__global__ __launch_bounds__(256, 2)
void gemm23_fused_kernel(const __half* __restrict__ H1, const __half* __restrict__ W2,
                         const __half* __restrict__ W3,
                         const float* __restrict__ b2, const float* __restrict__ b3,
                         float* __restrict__ H3,
                         const int* __restrict__ counts) {
    int g = blockIdx.z;
    int m0 = blockIdx.x * BM;
    if (m0 >= counts[g]) return;
    H1 += (size_t)g * BATCH * HID2;
    W2 += (size_t)g * HID * HID2;
    W3 += (size_t)g * HID * HID;
    b2 += (size_t)g * HID;
    b3 += (size_t)g * HID;
    H3 += (size_t)g * BATCH * HID;

    extern __shared__ __half smh[];
    __half* As  = smh;                  // [2][TSZ]
    __half* Bs  = smh + 2 * TSZ;        // [2][TSZ]
    __half* H2s = smh + 4 * TSZ;        // [128][LDH2]
    uint32_t as_u  = smem_u32(As);
    uint32_t bs_u  = smem_u32(Bs);
    uint32_t h2_u  = smem_u32(H2s);

    int tid  = threadIdx.x;
    int lane = tid & 31, warp = tid >> 5;
    int wm_base = (warp >> 1) * 32;
    int wn_base = (warp & 1) * 64;

    float acc[2][8][4];
    #pragma unroll
    for (int i = 0; i < 2; i++)
        #pragma unroll
        for (int j = 0; j < 8; j++)
            #pragma unroll
            for (int r = 0; r < 4; r++) acc[i][j][r] = 0.f;

    int lr = tid >> 3, lc = (tid & 7) * 8;

    int lane8 = lane & 7;
    uint32_t a_off[2], a2_off[2];
    #pragma unroll
    for (int wm = 0; wm < 2; wm++) {
        int row = wm_base + wm * 16 + lane8 + ((lane >> 3) & 1) * 8;
        int kof = (lane >> 4) * 8;
        a_off[wm]  = (uint32_t)((row * LDH  + kof) * 2);
        a2_off[wm] = (uint32_t)((row * LDH2 + kof) * 2);
    }
    uint32_t b_off[4];
    #pragma unroll
    for (int wnp = 0; wnp < 4; wnp++) {
        int row = wn_base + wnp * 16 + lane8 + (lane >> 4) * 8;
        int kof = ((lane >> 3) & 1) * 8;
        b_off[wnp] = (uint32_t)((row * LDH + kof) * 2);
    }

    auto stage1 = [&](int bsel, int k0) {
        uint32_t abase = as_u + (uint32_t)(bsel * TSZ) * 2;
        #pragma unroll
        for (int rr = 0; rr < 4; rr++) {
            int r = lr + rr * 32;
            cp_async16(abase + (uint32_t)(r * LDH + lc) * 2,
                       H1 + (size_t)(m0 + r) * HID2 + k0 + lc);
        }
        uint32_t bbase = bs_u + (uint32_t)(bsel * TSZ) * 2;
        #pragma unroll
        for (int rr = 0; rr < 4; rr++) {
            int n = lr + rr * 32;
            cp_async16(bbase + (uint32_t)(n * LDH + lc) * 2,
                       W2 + (size_t)n * HID2 + k0 + lc);
        }
    };
    auto stage_w3 = [&](int bsel, int k0) {
        uint32_t bbase = bs_u + (uint32_t)(bsel * TSZ) * 2;
        #pragma unroll
        for (int rr = 0; rr < 4; rr++) {
            int n = lr + rr * 32;
            cp_async16(bbase + (uint32_t)(n * LDH + lc) * 2,
                       W3 + (size_t)n * HID + k0 + lc);
        }
    };

    auto mma_block = [&](uint32_t ab, uint32_t bb, const uint32_t* aoff) {
        #pragma unroll
        for (int kk = 0; kk < 4; kk++) {
            uint32_t kb = (uint32_t)(kk * 16 * 2);
            uint32_t af[2][4], bf[4][4];
            ldsm_x4(ab + aoff[0] + kb, af[0]);
            ldsm_x4(ab + aoff[1] + kb, af[1]);
            #pragma unroll
            for (int wnp = 0; wnp < 4; wnp++)
                ldsm_x4(bb + b_off[wnp] + kb, bf[wnp]);
            #pragma unroll
            for (int wm = 0; wm < 2; wm++)
                #pragma unroll
                for (int wnp = 0; wnp < 4; wnp++) {
                    mma16(acc[wm][2 * wnp],     af[wm], &bf[wnp][0]);
                    mma16(acc[wm][2 * wnp + 1], af[wm], &bf[wnp][2]);
                }
        }
    };

    // ---- phase 1 mainloop (4 chunks, 2-stage) ----
    stage1(0, 0);
    CP_COMMIT();
    for (int c = 0; c < 4; c++) {
        int cur = c & 1;
        if (c < 3) {
            stage1(cur ^ 1, (c + 1) * BKH);
            CP_COMMIT();
            CP_WAIT(1);
        } else {
            stage_w3(0, 0);
            CP_COMMIT();
            CP_WAIT(1);
        }
        __syncthreads();
        mma_block(as_u + (uint32_t)(cur * TSZ) * 2, bs_u + (uint32_t)(cur * TSZ) * 2, a_off);
        __syncthreads();
    }

    // ---- phase-1 epilogue: relu(acc + b2) -> H2 smem tile ----
    #pragma unroll
    for (int wm = 0; wm < 2; wm++) {
        int r0 = wm_base + wm * 16 + (lane >> 2);
        #pragma unroll
        for (int wn = 0; wn < 8; wn++) {
            int c0 = wn_base + wn * 8 + 2 * (lane & 3);
            float b0 = b2[c0], b1v = b2[c0 + 1];
            float v0 = fmaxf(acc[wm][wn][0] + b0, 0.f);
            float v1 = fmaxf(acc[wm][wn][1] + b1v, 0.f);
            float v2 = fmaxf(acc[wm][wn][2] + b0, 0.f);
            float v3 = fmaxf(acc[wm][wn][3] + b1v, 0.f);
            *(__half2*)(H2s + r0 * LDH2 + c0)       = __floats2half2_rn(v0, v1);
            *(__half2*)(H2s + (r0 + 8) * LDH2 + c0) = __floats2half2_rn(v2, v3);
            acc[wm][wn][0] = 0.f; acc[wm][wn][1] = 0.f;
            acc[wm][wn][2] = 0.f; acc[wm][wn][3] = 0.f;
        }
    }
    stage_w3(1, BKH);
    CP_COMMIT();
    CP_WAIT(0);
    __syncthreads();

    // ---- phase 2 ----
    #pragma unroll
    for (int c2 = 0; c2 < 2; c2++) {
        uint32_t ab = h2_u + (uint32_t)(c2 * BKH) * 2;
        uint32_t bb = bs_u + (uint32_t)(c2 * TSZ) * 2;
        mma_block(ab, bb, a2_off);
    }

    #pragma unroll
    for (int wm = 0; wm < 2; wm++) {
        int r0 = wm_base + wm * 16 + (lane >> 2);
        #pragma unroll
        for (int wn = 0; wn < 8; wn++) {
            int c0 = wn_base + wn * 8 + 2 * (lane & 3);
            float b0 = b3[c0], b1v = b3[c0 + 1];
            float v0 = acc[wm][wn][0] + b0;
            float v1 = acc[wm][wn][1] + b1v;
            float v2 = acc[wm][wn][2] + b0;
            float v3 = acc[wm][wn][3] + b1v;
            *(float2*)(H3 + (size_t)(m0 + r0) * HID + c0)     = make_float2(v0, v1);
            *(float2*)(H3 + (size_t)(m0 + r0 + 8) * HID + c0) = make_float2(v2, v3);
        }
    }
}

// ---------------------------------------------------------------------------
// Weighted reduce (compacted): Rh[b,:] = fp16( sum_g w[b,g] * H3f[g, pos[b,g], :] )
// ---------------------------------------------------------------------------
__global__ __launch_bounds__(256)
void reduce_kernel(const float* __restrict__ H3, const float* __restrict__ w,
                   const int* __restrict__ pos, __half* __restrict__ Rh) {
    int idx = blockIdx.x * blockDim.x + threadIdx.x;
    int b = idx >> 5;
    int off = idx & 31;
    float4 r = make_float4(0.f, 0.f, 0.f, 0.f);
    const float4* H = (const float4*)H3;
    #pragma unroll
    for (int g = 0; g < NG; g++) {
        float wv = w[(size_t)b * NG + g];
        if (wv != 0.f) {
            int slot = pos[(size_t)b * NG + g];
            float4 h = H[((size_t)g * BATCH + slot) * 32 + off];
            r.x += wv * h.x; r.y += wv * h.y;
            r.z += wv * h.z; r.w += wv * h.w;
        }
    }
    __half2 p0 = __floats2half2_rn(r.x, r.y);
    __half2 p1 = __floats2half2_rn(r.z, r.w);
    uint2 p;
    p.x = *(uint32_t*)&p0;
    p.y = *(uint32_t*)&p1;
    ((uint2*)Rh)[idx] = p;
}

// ---------------------------------------------------------------------------
// Launch
// ---------------------------------------------------------------------------
extern "C" void kernel_launch(void* const* d_in, const int* in_sizes, int n_in,
                              void* d_out, int out_size) {
    (void)in_sizes; (void)n_in; (void)out_size;
    const float* X     = (const float*)d_in[0];
    const float* genre = (const float*)d_in[1];
    const float* W1    = (const float*)d_in[2];
    const float* b1    = (const float*)d_in[3];
    const float* W2    = (const float*)d_in[4];
    const float* b2    = (const float*)d_in[5];
    const float* W3    = (const float*)d_in[6];
    const float* b3    = (const float*)d_in[7];
    const float* Wa    = (const float*)d_in[8];
    const float* ba    = (const float*)d_in[9];
    const float* Wagg  = (const float*)d_in[10];
    const float* bagg  = (const float*)d_in[11];
    float* out = (float*)d_out;

    float *w, *H3f;
    __half *Xh, *W1h, *W2h, *W3h, *Waggh, *H1h, *Rh;
    int *counts, *idxArr, *pos;
    cudaGetSymbolAddress((void**)&w,      g_w);
    cudaGetSymbolAddress((void**)&Xh,     g_Xh);
    cudaGetSymbolAddress((void**)&W1h,    g_W1h);
    cudaGetSymbolAddress((void**)&W2h,    g_W2h);
    cudaGetSymbolAddress((void**)&W3h,    g_W3h);
    cudaGetSymbolAddress((void**)&Waggh,  g_Waggh);
    cudaGetSymbolAddress((void**)&H1h,    g_H1h);
    cudaGetSymbolAddress((void**)&H3f,    g_H3f);
    cudaGetSymbolAddress((void**)&Rh,     g_Rh);
    cudaGetSymbolAddress((void**)&counts, g_counts);
    cudaGetSymbolAddress((void**)&idxArr, g_idx);
    cudaGetSymbolAddress((void**)&pos,    g_pos);

    // Unconditional (idempotent, host-side, not captured) — no static guards.
    cudaFuncSetAttribute(gemm_fp16_kernel<1, 1, 1>,
                         cudaFuncAttributeMaxDynamicSharedMemorySize, GEMM_SMEM_BYTES);
    cudaFuncSetAttribute(gemm_fp16_kernel<1, 0, 3>,
                         cudaFuncAttributeMaxDynamicSharedMemorySize, GEMM_SMEM_BYTES);
    cudaFuncSetAttribute(gemm23_fused_kernel,
                         cudaFuncAttributeMaxDynamicSharedMemorySize, GEMM23_SMEM_BYTES);

    // 0) prep: fused weight transpose+cast, X cast, counts zero; compaction
    prep_kernel<<<PREP_TOTAL, 256>>>(W1, W2, W3, Wagg, X,
                                     W1h, W2h, W3h, Waggh, Xh, counts);
    compact_kernel<<<BATCH / 256, 256>>>(genre, counts, idxArr, pos);

    // 1) attention weights (masked)
    attn_kernel<<<BATCH / 64, 256>>>(X, genre, Wa, ba, w);

    // 2) H1c = relu(gather(Xh) @ W1[g]^T + b1[g]) -> fp16
    gemm_fp16_kernel<1, 1, 1><<<dim3(BATCH / BM, HID2 / BN, NG), 256, GEMM_SMEM_BYTES>>>(
        Xh, nullptr, W1h, b1, H1h,
        HID2, DIM, DIM,
        0LL, (long long)DIM * HID2, HID2, (long long)BATCH * HID2,
        idxArr, counts);

    // 3+4) fused: H3c = (relu(H1c @ W2^T + b2)) @ W3^T + b3 -> fp32
    gemm23_fused_kernel<<<dim3(BATCH / BM, 1, NG), 256, GEMM23_SMEM_BYTES>>>(
        H1h, W2h, W3h, b2, b3, H3f, counts);

    // 5) Rh = fp16( sum_g w .* H3c[pos] )
    reduce_kernel<<<(BATCH * 32) / 256, 256>>>(H3f, w, pos, Rh);

    // 6) out = relu([Xh, Rh] @ Wagg^T + bagg) -> fp32
    gemm_fp16_kernel<1, 0, 3><<<dim3(BATCH / BM, DIM / BN, 1), 256, GEMM_SMEM_BYTES>>>(
        Xh, Rh, Waggh, bagg, out,
        DIM, DAGG, DAGG,
        0LL, 0LL, 0LL, 0LL,
        idxArr, counts);
}

// round 14
// speedup vs baseline: 2.2065x; 1.1319x over previous
#include <cuda_runtime.h>
#include <cuda_fp16.h>
#include <cstdint>
#include <cstddef>

// Problem constants
#define BATCH   16384
#define DIM     512
#define HID     128     // H
#define HID2    256     // 2H
#define NG      18
#define DAGG    640     // D + H

// ---------------------------------------------------------------------------
// Scratch (device globals; allocation-free rule)
// ---------------------------------------------------------------------------
__device__ float  g_w[(size_t)BATCH * NG];                   // masked attention weights
__device__ __half g_Xh[(size_t)BATCH * DIM];                 // X cast to fp16
__device__ __half g_W1h[(size_t)NG * HID2 * DIM];            // weights n-major [g][N][K] fp16
__device__ __half g_W2h[(size_t)NG * HID * HID2];
__device__ __half g_W3h[(size_t)NG * HID * HID];
__device__ __half g_Waggh[(size_t)DIM * DAGG];               // [N=512][K=640]
__device__ __half g_Wah[(size_t)32 * DIM];                   // Wa padded n-major [32][512]
__device__ __half g_H1h[(size_t)NG * BATCH * HID2];          // H1 compacted, fp16
__device__ __half g_H3h[(size_t)NG * BATCH * HID];           // H3 compacted, fp16
__device__ __half g_Rh[(size_t)BATCH * HID];                 // refinements fp16
__device__ int    g_counts[32];                              // members per genre
__device__ int    g_idx[(size_t)NG * BATCH];                 // genre -> member rows
__device__ int    g_pos[(size_t)BATCH * NG];                 // (b,g) -> slot

// ---------------------------------------------------------------------------
// Helpers
// ---------------------------------------------------------------------------
__device__ __forceinline__ uint32_t smem_u32(const void* p) {
    uint32_t a;
    asm("{ .reg .u64 t; cvta.to.shared.u64 t, %1; cvt.u32.u64 %0, t; }" : "=r"(a) : "l"(p));
    return a;
}
__device__ __forceinline__ void cp_async16(uint32_t dst, const void* src) {
    asm volatile("cp.async.cg.shared.global [%0], [%1], 16;" :: "r"(dst), "l"(src) : "memory");
}
#define CP_COMMIT() asm volatile("cp.async.commit_group;" ::: "memory")
#define CP_WAIT(n)  asm volatile("cp.async.wait_group %0;" :: "n"(n) : "memory")

__device__ __forceinline__ void ldsm_x4(uint32_t addr, uint32_t* r) {
    asm volatile("ldmatrix.sync.aligned.m8n8.x4.shared.b16 {%0,%1,%2,%3}, [%4];"
        : "=r"(r[0]), "=r"(r[1]), "=r"(r[2]), "=r"(r[3]) : "r"(addr));
}

// fp16 MMA m16n8k16, fp32 accumulate
__device__ __forceinline__ void mma16(float* d, const uint32_t* a, const uint32_t* b) {
    asm volatile(
        "mma.sync.aligned.m16n8k16.row.col.f32.f16.f16.f32 "
        "{%0,%1,%2,%3}, {%4,%5,%6,%7}, {%8,%9}, {%0,%1,%2,%3};"
        : "+f"(d[0]), "+f"(d[1]), "+f"(d[2]), "+f"(d[3])
        : "r"(a[0]), "r"(a[1]), "r"(a[2]), "r"(a[3]), "r"(b[0]), "r"(b[1]));
}

// ---------------------------------------------------------------------------
// Prep (fused): weight transpose+cast tiles, X cast, counts zeroing, Wa pad.
//   blocks [0, 3488): 32x32 transpose+cast tiles over W1|W2|W3|Wagg
//   blocks [3488, 4000): grid-stride fp32->fp16 cast of X (block 3488 zeroes counts)
//   blocks [4000, 4016): Wa [512][18] -> Wah [32][512] n-major fp16, zero-padded
// ---------------------------------------------------------------------------
#define PREP_TILES 3488
#define PREP_CAST  512
#define PREP_WAH   16
#define PREP_TOTAL (PREP_TILES + PREP_CAST + PREP_WAH)

__global__ __launch_bounds__(256)
void prep_kernel(const float* __restrict__ W1, const float* __restrict__ W2,
                 const float* __restrict__ W3, const float* __restrict__ Wagg,
                 const float* __restrict__ X, const float* __restrict__ Wa,
                 __half* __restrict__ W1h, __half* __restrict__ W2h,
                 __half* __restrict__ W3h, __half* __restrict__ Waggh,
                 __half* __restrict__ Xh, __half* __restrict__ Wah,
                 int* __restrict__ counts) {
    int bz = blockIdx.x;
    int tid = threadIdx.x;

    if (bz >= PREP_TILES + PREP_CAST) {
        // Wa pad region: 16 blocks x 32 k-rows
        int kb = (bz - PREP_TILES - PREP_CAST) * 32;
        for (int e = tid; e < 32 * 32; e += 256) {
            int k = kb + (e >> 5), n = e & 31;
            float v = (n < NG) ? Wa[(size_t)k * NG + n] : 0.f;
            Wah[(size_t)n * DIM + k] = __float2half_rn(v);
        }
        return;
    }
    if (bz >= PREP_TILES) {
        // X cast region
        int local = bz - PREP_TILES;
        if (local == 0 && tid < 32) counts[tid] = 0;
        int n4 = BATCH * DIM / 4;
        for (int i = local * 256 + tid; i < n4; i += PREP_CAST * 256) {
            float4 v = ((const float4*)X)[i];
            __half2 h0 = __floats2half2_rn(v.x, v.y);
            __half2 h1 = __floats2half2_rn(v.z, v.w);
            uint2 p;
            p.x = *(uint32_t*)&h0;
            p.y = *(uint32_t*)&h1;
            ((uint2*)Xh)[i] = p;
        }
        return;
    }

    __shared__ float t[32][33];
    const float* in;
    __half* out;
    int K, N, g, tt;
    if (bz < 2304)      { g = bz / 128;          tt = bz % 128; in = W1;   out = W1h;   K = DIM;  N = HID2; }
    else if (bz < 2880) { bz -= 2304; g = bz / 32; tt = bz % 32; in = W2;   out = W2h;   K = HID2; N = HID;  }
    else if (bz < 3168) { bz -= 2880; g = bz / 16; tt = bz % 16; in = W3;   out = W3h;   K = HID;  N = HID;  }
    else                { bz -= 3168; g = 0;       tt = bz;      in = Wagg; out = Waggh; K = DAGG; N = DIM;  }
    in  += (size_t)g * K * N;
    out += (size_t)g * K * N;
    int ntn = N / 32;
    int k0 = (tt / ntn) * 32;
    int n0 = (tt % ntn) * 32;
    int tx = tid & 31, ty = tid >> 5;   // 32 x 8
    #pragma unroll
    for (int i = 0; i < 4; i++) {
        int r = ty + i * 8;
        t[r][tx] = in[(size_t)(k0 + r) * N + n0 + tx];
    }
    __syncthreads();
    #pragma unroll
    for (int i = 0; i < 4; i++) {
        int r = ty + i * 8;
        out[(size_t)(n0 + r) * K + k0 + tx] = __float2half_rn(t[tx][r]);
    }
}

// ---------------------------------------------------------------------------
// Membership compaction, coalesced
// ---------------------------------------------------------------------------
__global__ __launch_bounds__(256)
void compact_kernel(const float* __restrict__ genre, int* __restrict__ counts,
                    int* __restrict__ idxArr, int* __restrict__ pos) {
    __shared__ float gt[256][19];
    __shared__ int   ps[256][19];
    int b0 = blockIdx.x * 256;
    int tid = threadIdx.x;
    for (int i = tid; i < 256 * NG; i += 256) {
        gt[i / NG][i % NG] = genre[(size_t)b0 * NG + i];
    }
    __syncthreads();
    int warp = tid >> 5, lane = tid & 31;
    for (int g = warp; g < NG; g += 8) {
        unsigned masks[8];
        int total = 0;
        #pragma unroll
        for (int s = 0; s < 8; s++) {
            float v = gt[s * 32 + lane][g];
            masks[s] = __ballot_sync(0xffffffffu, v > 0.f);
            total += __popc(masks[s]);
        }
        int base = 0;
        if (lane == 0) base = atomicAdd(&counts[g], total);
        base = __shfl_sync(0xffffffffu, base, 0);
        int run = 0;
        #pragma unroll
        for (int s = 0; s < 8; s++) {
            unsigned m = masks[s];
            if (m & (1u << lane)) {
                int slot = base + run + __popc(m & ((1u << lane) - 1u));
                idxArr[(size_t)g * BATCH + slot] = b0 + s * 32 + lane;
                ps[s * 32 + lane][g] = slot;
            }
            run += __popc(m);
        }
    }
    __syncthreads();
    for (int i = tid; i < 256 * NG; i += 256) {
        pos[(size_t)b0 * NG + i] = ps[i / NG][i % NG];
    }
}

// ---------------------------------------------------------------------------
// Tensor-core attention: logits = Xh @ Wah^T (N=32, 18 real), softmax over 18,
// mask by membership. 128 rows per block, 8 warps (16 rows each).
// ---------------------------------------------------------------------------
#define AT_LDH 72
#define AT_ASZ (128 * AT_LDH)   // halves per A stage
#define AT_BSZ (32 * AT_LDH)    // halves per B stage
#define AT_CT_OFF (2 * AT_ASZ + 2 * AT_BSZ)          // in halves
#define AT_SMEM (AT_CT_OFF * 2 + 128 * 33 * 4)       // bytes

__global__ __launch_bounds__(256)
void attn_tc_kernel(const __half* __restrict__ Xh, const __half* __restrict__ Wah,
                    const float* __restrict__ ba, const float* __restrict__ genre,
                    float* __restrict__ w) {
    extern __shared__ __half smh[];
    __half* As = smh;                       // [2][AT_ASZ]
    __half* Bs = smh + 2 * AT_ASZ;          // [2][AT_BSZ]
    float*  Ct = (float*)(smh + AT_CT_OFF); // [128][33]
    uint32_t as_u = smem_u32(As);
    uint32_t bs_u = smem_u32(Bs);

    int m0 = blockIdx.x * 128;
    int tid = threadIdx.x;
    int lane = tid & 31, warp = tid >> 5;

    float acc[4][4];
    #pragma unroll
    for (int i = 0; i < 4; i++)
        #pragma unroll
        for (int r = 0; r < 4; r++) acc[i][r] = 0.f;

    int lr = tid >> 3, lc = (tid & 7) * 8;

    int lane8 = lane & 7;
    // A fragment: warp's 16 rows
    uint32_t a_off = (uint32_t)(((16 * warp + lane8 + ((lane >> 3) & 1) * 8) * AT_LDH
                                 + (lane >> 4) * 8) * 2);
    // B fragments: n-groups 0 and 16
    uint32_t b_off[2];
    #pragma unroll
    for (int p = 0; p < 2; p++)
        b_off[p] = (uint32_t)(((p * 16 + lane8 + (lane >> 4) * 8) * AT_LDH
                               + ((lane >> 3) & 1) * 8) * 2);

    auto stage = [&](int bsel, int k0) {
        uint32_t abase = as_u + (uint32_t)(bsel * AT_ASZ) * 2;
        #pragma unroll
        for (int rr = 0; rr < 4; rr++) {
            int r = lr + rr * 32;
            cp_async16(abase + (uint32_t)(r * AT_LDH + lc) * 2,
                       Xh + (size_t)(m0 + r) * DIM + k0 + lc);
        }
        // B: 32 n-rows, one pass (256 threads x 16B = 8KB exactly covers 32x64x2B)
        uint32_t bbase = bs_u + (uint32_t)(bsel * AT_BSZ) * 2;
        int n = tid >> 3;
        cp_async16(bbase + (uint32_t)(n * AT_LDH + lc) * 2,
                   Wah + (size_t)n * DIM + k0 + lc);
    };

    stage(0, 0);
    CP_COMMIT();
    for (int c = 0; c < 8; c++) {   // K = 512 / 64
        int cur = c & 1;
        if (c < 7) {
            stage(cur ^ 1, (c + 1) * 64);
            CP_COMMIT();
            CP_WAIT(1);
        } else {
            CP_WAIT(0);
        }
        __syncthreads();
        uint32_t ab = as_u + (uint32_t)(cur * AT_ASZ) * 2;
        uint32_t bb = bs_u + (uint32_t)(cur * AT_BSZ) * 2;
        #pragma unroll
        for (int kk = 0; kk < 4; kk++) {
            uint32_t kb = (uint32_t)(kk * 16 * 2);
            uint32_t af[4], bf[2][4];
            ldsm_x4(ab + a_off + kb, af);
            ldsm_x4(bb + b_off[0] + kb, bf[0]);
            ldsm_x4(bb + b_off[1] + kb, bf[1]);
            mma16(acc[0], af, &bf[0][0]);
            mma16(acc[1], af, &bf[0][2]);
            mma16(acc[2], af, &bf[1][0]);
            mma16(acc[3], af, &bf[1][2]);
        }
        __syncthreads();
    }

    // C fragments -> smem tile [128][33]
    #pragma unroll
    for (int wn = 0; wn < 4; wn++) {
        int c0 = wn * 8 + 2 * (lane & 3);
        int r0 = 16 * warp + (lane >> 2);
        Ct[r0 * 33 + c0]       = acc[wn][0];
        Ct[r0 * 33 + c0 + 1]   = acc[wn][1];
        Ct[(r0 + 8) * 33 + c0]     = acc[wn][2];
        Ct[(r0 + 8) * 33 + c0 + 1] = acc[wn][3];
    }
    __syncthreads();

    // softmax over the 18 real genres + membership mask
    if (tid < 128) {
        int b = m0 + tid;
        float l[NG];
        float mx = -1e30f;
        #pragma unroll
        for (int g = 0; g < NG; g++) {
            l[g] = Ct[tid * 33 + g] + ba[g];
            mx = fmaxf(mx, l[g]);
        }
        float s = 0.f;
        #pragma unroll
        for (int g = 0; g < NG; g++) {
            l[g] = expf(l[g] - mx);
            s += l[g];
        }
        float inv = 1.f / s;
        #pragma unroll
        for (int g = 0; g < NG; g++) {
            float gv = genre[(size_t)b * NG + g];
            w[(size_t)b * NG + g] = (gv > 0.f) ? l[g] * inv * gv : 0.f;
        }
    }
}

// ---------------------------------------------------------------------------
// Shared GEMM geometry
// ---------------------------------------------------------------------------
#define BM  128
#define BN  128
#define BKH 64
#define LDH 72
#define TSZ (128 * LDH)
#define NSTAGE 3
#define GEMM_SMEM_BYTES (2 * NSTAGE * TSZ * 2)

// ---------------------------------------------------------------------------
// fp16 GEMM (general, 3-stage pipeline, one barrier per chunk)
// ---------------------------------------------------------------------------
template<int ACT, int OUTH, int MODE>
__global__ __launch_bounds__(256, 2)
void gemm_fp16_kernel(const __half* __restrict__ A, const __half* __restrict__ Rp,
                      const __half* __restrict__ W, const float* __restrict__ bias,
                      void* __restrict__ Cv,
                      int N, int K, int lda,
                      long long sA, long long sW, long long sB, long long sC,
                      const int* __restrict__ idxArr, const int* __restrict__ counts) {
    int g = blockIdx.z;
    int m0 = blockIdx.x * BM;
    int cnt = 0;
    if (MODE == 1) {
        cnt = counts[g];
        if (m0 >= cnt) return;
    }
    A    += (size_t)g * sA;
    W    += (size_t)g * sW;
    bias += (size_t)g * sB;
    const int* gidx = idxArr + (size_t)g * BATCH;

    extern __shared__ __half smh[];
    __half* As = smh;
    __half* Bs = smh + NSTAGE * TSZ;
    uint32_t as_u = smem_u32(As);
    uint32_t bs_u = smem_u32(Bs);

    int tid  = threadIdx.x;
    int n0   = blockIdx.y * BN;
    int lane = tid & 31, warp = tid >> 5;
    int wm_base = (warp >> 1) * 32;
    int wn_base = (warp & 1) * 64;

    float acc[2][8][4];
    #pragma unroll
    for (int i = 0; i < 2; i++)
        #pragma unroll
        for (int j = 0; j < 8; j++)
            #pragma unroll
            for (int r = 0; r < 4; r++) acc[i][j][r] = 0.f;

    int lr = tid >> 3, lc = (tid & 7) * 8;

    const __half* arow_ptr[4];
    #pragma unroll
    for (int rr = 0; rr < 4; rr++) {
        int grow = m0 + lr + rr * 32;
        if (MODE == 1) {
            int cl = (grow < cnt) ? grow : (cnt - 1);
            arow_ptr[rr] = A + (size_t)gidx[cl] * lda;
        } else {
            arow_ptr[rr] = A + (size_t)grow * lda;
        }
    }

    int lane8 = lane & 7;
    uint32_t a_off[2];
    #pragma unroll
    for (int wm = 0; wm < 2; wm++) {
        int row = wm_base + wm * 16 + lane8 + ((lane >> 3) & 1) * 8;
        int kof = (lane >> 4) * 8;
        a_off[wm] = (uint32_t)((row * LDH + kof) * 2);
    }
    uint32_t b_off[4];
    #pragma unroll
    for (int wnp = 0; wnp < 4; wnp++) {
        int row = wn_base + wnp * 16 + lane8 + (lane >> 4) * 8;
        int kof = ((lane >> 3) & 1) * 8;
        b_off[wnp] = (uint32_t)((row * LDH + kof) * 2);
    }

    int nchunks = K / BKH;

    auto stage = [&](int bsel, int k0) {
        uint32_t abase = as_u + (uint32_t)(bsel * TSZ) * 2;
        #pragma unroll
        for (int rr = 0; rr < 4; rr++) {
            int r = lr + rr * 32;
            int gcol = k0 + lc;
            const __half* src;
            if (MODE == 3) {
                int grow = m0 + r;
                src = (gcol < DIM) ? (A + (size_t)grow * DIM + gcol)
                                   : (Rp + (size_t)grow * HID + (gcol - DIM));
            } else {
                src = arow_ptr[rr] + gcol;
            }
            cp_async16(abase + (uint32_t)(r * LDH + lc) * 2, src);
        }
        uint32_t bbase = bs_u + (uint32_t)(bsel * TSZ) * 2;
        #pragma unroll
        for (int rr = 0; rr < 4; rr++) {
            int n = lr + rr * 32;
            cp_async16(bbase + (uint32_t)(n * LDH + lc) * 2,
                       W + (size_t)(n0 + n) * K + k0 + lc);
        }
    };

    stage(0, 0);
    CP_COMMIT();
    if (nchunks > 1) {
        stage(1, BKH);
        CP_COMMIT();
    }

    for (int c = 0; c < nchunks; c++) {
        if (c + 1 < nchunks) { CP_WAIT(1); } else { CP_WAIT(0); }
        __syncthreads();
        if (c + 2 < nchunks) {
            stage((c + 2) % NSTAGE, (c + 2) * BKH);
            CP_COMMIT();
        }
        int cur = c % NSTAGE;
        uint32_t ab = as_u + (uint32_t)(cur * TSZ) * 2;
        uint32_t bb = bs_u + (uint32_t)(cur * TSZ) * 2;

        #pragma unroll
        for (int kk = 0; kk < 4; kk++) {
            uint32_t kb = (uint32_t)(kk * 16 * 2);
            uint32_t af[2][4], bf[4][4];
            ldsm_x4(ab + a_off[0] + kb, af[0]);
            ldsm_x4(ab + a_off[1] + kb, af[1]);
            #pragma unroll
            for (int wnp = 0; wnp < 4; wnp++)
                ldsm_x4(bb + b_off[wnp] + kb, bf[wnp]);
            #pragma unroll
            for (int wm = 0; wm < 2; wm++)
                #pragma unroll
                for (int wnp = 0; wnp < 4; wnp++) {
                    mma16(acc[wm][2 * wnp],     af[wm], &bf[wnp][0]);
                    mma16(acc[wm][2 * wnp + 1], af[wm], &bf[wnp][2]);
                }
        }
    }

    #pragma unroll
    for (int wm = 0; wm < 2; wm++) {
        int r0 = m0 + wm_base + wm * 16 + (lane >> 2);
        #pragma unroll
        for (int wn = 0; wn < 8; wn++) {
            int c0 = n0 + wn_base + wn * 8 + 2 * (lane & 3);
            float b0 = bias[c0], b1v = bias[c0 + 1];
            float v0 = acc[wm][wn][0] + b0;
            float v1 = acc[wm][wn][1] + b1v;
            float v2 = acc[wm][wn][2] + b0;
            float v3 = acc[wm][wn][3] + b1v;
            if (ACT) {
                v0 = fmaxf(v0, 0.f); v1 = fmaxf(v1, 0.f);
                v2 = fmaxf(v2, 0.f); v3 = fmaxf(v3, 0.f);
            }
            if (OUTH) {
                __half* C = (__half*)Cv + (size_t)g * sC;
                __half2 p0 = __floats2half2_rn(v0, v1);
                __half2 p1 = __floats2half2_rn(v2, v3);
                *(__half2*)(C + (size_t)r0 * N + c0)       = p0;
                *(__half2*)(C + (size_t)(r0 + 8) * N + c0) = p1;
            } else {
                float* C = (float*)Cv + (size_t)g * sC;
                *(float2*)(C + (size_t)r0 * N + c0)       = make_float2(v0, v1);
                *(float2*)(C + (size_t)(r0 + 8) * N + c0) = make_float2(v2, v3);
            }
        }
    }
}

// ---------------------------------------------------------------------------
// Fused GEMM2+GEMM3 (H3 now written as fp16)
// ---------------------------------------------------------------------------
#define LDH2 136
#define H2TSZ (128 * LDH2)
#define G23_STAGE_BYTES (4 * TSZ * 2)
#define GEMM23_SMEM_BYTES (G23_STAGE_BYTES + H2TSZ * 2)

__global__ __launch_bounds__(256, 2)
void gemm23_fused_kernel(const __half* __restrict__ H1, const __half* __restrict__ W2,
                         const __half* __restrict__ W3,
                         const float* __restrict__ b2, const float* __restrict__ b3,
                         __half* __restrict__ H3,
                         const int* __restrict__ counts) {
    int g = blockIdx.z;
    int m0 = blockIdx.x * BM;
    if (m0 >= counts[g]) return;
    H1 += (size_t)g * BATCH * HID2;
    W2 += (size_t)g * HID * HID2;
    W3 += (size_t)g * HID * HID;
    b2 += (size_t)g * HID;
    b3 += (size_t)g * HID;
    H3 += (size_t)g * BATCH * HID;

    extern __shared__ __half smh[];
    __half* As  = smh;
    __half* Bs  = smh + 2 * TSZ;
    __half* H2s = smh + 4 * TSZ;
    uint32_t as_u  = smem_u32(As);
    uint32_t bs_u  = smem_u32(Bs);
    uint32_t h2_u  = smem_u32(H2s);

    int tid  = threadIdx.x;
    int lane = tid & 31, warp = tid >> 5;
    int wm_base = (warp >> 1) * 32;
    int wn_base = (warp & 1) * 64;

    float acc[2][8][4];
    #pragma unroll
    for (int i = 0; i < 2; i++)
        #pragma unroll
        for (int j = 0; j < 8; j++)
            #pragma unroll
            for (int r = 0; r < 4; r++) acc[i][j][r] = 0.f;

    int lr = tid >> 3, lc = (tid & 7) * 8;

    int lane8 = lane & 7;
    uint32_t a_off[2], a2_off[2];
    #pragma unroll
    for (int wm = 0; wm < 2; wm++) {
        int row = wm_base + wm * 16 + lane8 + ((lane >> 3) & 1) * 8;
        int kof = (lane >> 4) * 8;
        a_off[wm]  = (uint32_t)((row * LDH  + kof) * 2);
        a2_off[wm] = (uint32_t)((row * LDH2 + kof) * 2);
    }
    uint32_t b_off[4];
    #pragma unroll
    for (int wnp = 0; wnp < 4; wnp++) {
        int row = wn_base + wnp * 16 + lane8 + (lane >> 4) * 8;
        int kof = ((lane >> 3) & 1) * 8;
        b_off[wnp] = (uint32_t)((row * LDH + kof) * 2);
    }

    auto stage1 = [&](int bsel, int k0) {
        uint32_t abase = as_u + (uint32_t)(bsel * TSZ) * 2;
        #pragma unroll
        for (int rr = 0; rr < 4; rr++) {
            int r = lr + rr * 32;
            cp_async16(abase + (uint32_t)(r * LDH + lc) * 2,
                       H1 + (size_t)(m0 + r) * HID2 + k0 + lc);
        }
        uint32_t bbase = bs_u + (uint32_t)(bsel * TSZ) * 2;
        #pragma unroll
        for (int rr = 0; rr < 4; rr++) {
            int n = lr + rr * 32;
            cp_async16(bbase + (uint32_t)(n * LDH + lc) * 2,
                       W2 + (size_t)n * HID2 + k0 + lc);
        }
    };
    auto stage_w3 = [&](int bsel, int k0) {
        uint32_t bbase = bs_u + (uint32_t)(bsel * TSZ) * 2;
        #pragma unroll
        for (int rr = 0; rr < 4; rr++) {
            int n = lr + rr * 32;
            cp_async16(bbase + (uint32_t)(n * LDH + lc) * 2,
                       W3 + (size_t)n * HID + k0 + lc);
        }
    };

    auto mma_block = [&](uint32_t ab, uint32_t bb, const uint32_t* aoff) {
        #pragma unroll
        for (int kk = 0; kk < 4; kk++) {
            uint32_t kb = (uint32_t)(kk * 16 * 2);
            uint32_t af[2][4], bf[4][4];
            ldsm_x4(ab + aoff[0] + kb, af[0]);
            ldsm_x4(ab + aoff[1] + kb, af[1]);
            #pragma unroll
            for (int wnp = 0; wnp < 4; wnp++)
                ldsm_x4(bb + b_off[wnp] + kb, bf[wnp]);
            #pragma unroll
            for (int wm = 0; wm < 2; wm++)
                #pragma unroll
                for (int wnp = 0; wnp < 4; wnp++) {
                    mma16(acc[wm][2 * wnp],     af[wm], &bf[wnp][0]);
                    mma16(acc[wm][2 * wnp + 1], af[wm], &bf[wnp][2]);
                }
        }
    };

    stage1(0, 0);
    CP_COMMIT();
    for (int c = 0; c < 4; c++) {
        int cur = c & 1;
        if (c < 3) {
            stage1(cur ^ 1, (c + 1) * BKH);
            CP_COMMIT();
            CP_WAIT(1);
        } else {
            stage_w3(0, 0);
            CP_COMMIT();
            CP_WAIT(1);
        }
        __syncthreads();
        mma_block(as_u + (uint32_t)(cur * TSZ) * 2, bs_u + (uint32_t)(cur * TSZ) * 2, a_off);
        __syncthreads();
    }

    #pragma unroll
    for (int wm = 0; wm < 2; wm++) {
        int r0 = wm_base + wm * 16 + (lane >> 2);
        #pragma unroll
        for (int wn = 0; wn < 8; wn++) {
            int c0 = wn_base + wn * 8 + 2 * (lane & 3);
            float b0 = b2[c0], b1v = b2[c0 + 1];
            float v0 = fmaxf(acc[wm][wn][0] + b0, 0.f);
            float v1 = fmaxf(acc[wm][wn][1] + b1v, 0.f);
            float v2 = fmaxf(acc[wm][wn][2] + b0, 0.f);
            float v3 = fmaxf(acc[wm][wn][3] + b1v, 0.f);
            *(__half2*)(H2s + r0 * LDH2 + c0)       = __floats2half2_rn(v0, v1);
            *(__half2*)(H2s + (r0 + 8) * LDH2 + c0) = __floats2half2_rn(v2, v3);
            acc[wm][wn][0] = 0.f; acc[wm][wn][1] = 0.f;
            acc[wm][wn][2] = 0.f; acc[wm][wn][3] = 0.f;
        }
    }
    stage_w3(1, BKH);
    CP_COMMIT();
    CP_WAIT(0);
    __syncthreads();

    #pragma unroll
    for (int c2 = 0; c2 < 2; c2++) {
        uint32_t ab = h2_u + (uint32_t)(c2 * BKH) * 2;
        uint32_t bb = bs_u + (uint32_t)(c2 * TSZ) * 2;
        mma_block(ab, bb, a2_off);
    }

    // phase-2 epilogue -> fp16 H3
    #pragma unroll
    for (int wm = 0; wm < 2; wm++) {
        int r0 = wm_base + wm * 16 + (lane >> 2);
        #pragma unroll
        for (int wn = 0; wn < 8; wn++) {
            int c0 = wn_base + wn * 8 + 2 * (lane & 3);
            float b0 = b3[c0], b1v = b3[c0 + 1];
            float v0 = acc[wm][wn][0] + b0;
            float v1 = acc[wm][wn][1] + b1v;
            float v2 = acc[wm][wn][2] + b0;
            float v3 = acc[wm][wn][3] + b1v;
            *(__half2*)(H3 + (size_t)(m0 + r0) * HID + c0)     = __floats2half2_rn(v0, v1);
            *(__half2*)(H3 + (size_t)(m0 + r0 + 8) * HID + c0) = __floats2half2_rn(v2, v3);
        }
    }
}

// ---------------------------------------------------------------------------
// Weighted reduce (compacted, fp16 H3): Rh[b] = fp16( sum_g w[b,g]*H3[g,pos] )
// ---------------------------------------------------------------------------
__global__ __launch_bounds__(256)
void reduce_kernel(const __half* __restrict__ H3, const float* __restrict__ w,
                   const int* __restrict__ pos, __half* __restrict__ Rh) {
    int idx = blockIdx.x * blockDim.x + threadIdx.x;   // BATCH * 32
    int b = idx >> 5;
    int off = idx & 31;
    float r0 = 0.f, r1 = 0.f, r2 = 0.f, r3 = 0.f;
    const uint2* H = (const uint2*)H3;
    #pragma unroll
    for (int g = 0; g < NG; g++) {
        float wv = w[(size_t)b * NG + g];
        if (wv != 0.f) {
            int slot = pos[(size_t)b * NG + g];
            uint2 h = H[((size_t)g * BATCH + slot) * 32 + off];
            float2 f0 = __half22float2(*(__half2*)&h.x);
            float2 f1 = __half22float2(*(__half2*)&h.y);
            r0 += wv * f0.x; r1 += wv * f0.y;
            r2 += wv * f1.x; r3 += wv * f1.y;
        }
    }
    __half2 p0 = __floats2half2_rn(r0, r1);
    __half2 p1 = __floats2half2_rn(r2, r3);
    uint2 p;
    p.x = *(uint32_t*)&p0;
    p.y = *(uint32_t*)&p1;
    ((uint2*)Rh)[idx] = p;
}

// ---------------------------------------------------------------------------
// Launch
// ---------------------------------------------------------------------------
extern "C" void kernel_launch(void* const* d_in, const int* in_sizes, int n_in,
                              void* d_out, int out_size) {
    (void)in_sizes; (void)n_in; (void)out_size;
    const float* X     = (const float*)d_in[0];
    const float* genre = (const float*)d_in[1];
    const float* W1    = (const float*)d_in[2];
    const float* b1    = (const float*)d_in[3];
    const float* W2    = (const float*)d_in[4];
    const float* b2    = (const float*)d_in[5];
    const float* W3    = (const float*)d_in[6];
    const float* b3    = (const float*)d_in[7];
    const float* Wa    = (const float*)d_in[8];
    const float* ba    = (const float*)d_in[9];
    const float* Wagg  = (const float*)d_in[10];
    const float* bagg  = (const float*)d_in[11];
    float* out = (float*)d_out;

    float *w;
    __half *Xh, *W1h, *W2h, *W3h, *Waggh, *Wah, *H1h, *H3h, *Rh;
    int *counts, *idxArr, *pos;
    cudaGetSymbolAddress((void**)&w,      g_w);
    cudaGetSymbolAddress((void**)&Xh,     g_Xh);
    cudaGetSymbolAddress((void**)&W1h,    g_W1h);
    cudaGetSymbolAddress((void**)&W2h,    g_W2h);
    cudaGetSymbolAddress((void**)&W3h,    g_W3h);
    cudaGetSymbolAddress((void**)&Waggh,  g_Waggh);
    cudaGetSymbolAddress((void**)&Wah,    g_Wah);
    cudaGetSymbolAddress((void**)&H1h,    g_H1h);
    cudaGetSymbolAddress((void**)&H3h,    g_H3h);
    cudaGetSymbolAddress((void**)&Rh,     g_Rh);
    cudaGetSymbolAddress((void**)&counts, g_counts);
    cudaGetSymbolAddress((void**)&idxArr, g_idx);
    cudaGetSymbolAddress((void**)&pos,    g_pos);

    cudaFuncSetAttribute(gemm_fp16_kernel<1, 1, 1>,
                         cudaFuncAttributeMaxDynamicSharedMemorySize, GEMM_SMEM_BYTES);
    cudaFuncSetAttribute(gemm_fp16_kernel<1, 0, 3>,
                         cudaFuncAttributeMaxDynamicSharedMemorySize, GEMM_SMEM_BYTES);
    cudaFuncSetAttribute(gemm23_fused_kernel,
                         cudaFuncAttributeMaxDynamicSharedMemorySize, GEMM23_SMEM_BYTES);
    cudaFuncSetAttribute(attn_tc_kernel,
                         cudaFuncAttributeMaxDynamicSharedMemorySize, AT_SMEM);

    // 0) prep + compaction
    prep_kernel<<<PREP_TOTAL, 256>>>(W1, W2, W3, Wagg, X, Wa,
                                     W1h, W2h, W3h, Waggh, Xh, Wah, counts);
    compact_kernel<<<BATCH / 256, 256>>>(genre, counts, idxArr, pos);

    // 1) attention weights via tensor cores
    attn_tc_kernel<<<BATCH / 128, 256, AT_SMEM>>>(Xh, Wah, ba, genre, w);

    // 2) H1c = relu(gather(Xh) @ W1[g]^T + b1[g]) -> fp16
    gemm_fp16_kernel<1, 1, 1><<<dim3(BATCH / BM, HID2 / BN, NG), 256, GEMM_SMEM_BYTES>>>(
        Xh, nullptr, W1h, b1, H1h,
        HID2, DIM, DIM,
        0LL, (long long)DIM * HID2, HID2, (long long)BATCH * HID2,
        idxArr, counts);

    // 3+4) fused: H3c = (relu(H1c @ W2^T + b2)) @ W3^T + b3 -> fp16
    gemm23_fused_kernel<<<dim3(BATCH / BM, 1, NG), 256, GEMM23_SMEM_BYTES>>>(
        H1h, W2h, W3h, b2, b3, H3h, counts);

    // 5) Rh = fp16( sum_g w .* H3c[pos] )
    reduce_kernel<<<(BATCH * 32) / 256, 256>>>(H3h, w, pos, Rh);

    // 6) out = relu([Xh, Rh] @ Wagg^T + bagg) -> fp32
    gemm_fp16_kernel<1, 0, 3><<<dim3(BATCH / BM, DIM / BN, 1), 256, GEMM_SMEM_BYTES>>>(
        Xh, Rh, Waggh, bagg, out,
        DIM, DAGG, DAGG,
        0LL, 0LL, 0LL, 0LL,
        idxArr, counts);
}